// round 1
// baseline (speedup 1.0000x reference)
#include <cuda_runtime.h>
#include <math.h>

#define HW 4096         // 64*64 spatial positions at feature res
#define CF 256          // feature channels
#define CO 64           // value channels (unalign_fb)
#define ALPHA 100.0f

// ---------------- device scratch (allocation-free) ----------------
__device__ float g_X[(size_t)HW * HW];   // X[p][q] = exp(alpha * S[q,p]), 64 MB
__device__ float g_faT[HW * CF];         // normalized fa, [p][c]
__device__ float g_fbT[HW * CF];         // normalized fb, [q][c]
__device__ float g_ufb[HW * CO];         // downsampled values, [q][c]
__device__ float g_meanA[CF];
__device__ float g_meanB[CF];
__device__ unsigned char g_maskA[3 * HW];
__device__ unsigned char g_codeB[HW];    // 3-bit code of mask_b per q
__device__ float g_H[8 * HW];            // H[code][p] = sum_{q:code} X[p][q]
__device__ float g_U0[CO];               // sum_q ufb[q][c]
__device__ float g_UB[8 * CO];           // UB[code][c]
__device__ float g_cnt[8];               // count of q per code
__device__ float g_aligned[HW * CO];     // [p][c]

// ---------------- small float4 helpers ----------------
__device__ __forceinline__ float4 f4z() { return make_float4(0.f, 0.f, 0.f, 0.f); }
__device__ __forceinline__ float4 f4add(float4 a, float4 b) {
    a.x += b.x; a.y += b.y; a.z += b.z; a.w += b.w; return a;
}
__device__ __forceinline__ float4 f4sub(float4 a, float4 b) {
    a.x -= b.x; a.y -= b.y; a.z -= b.z; a.w -= b.w; return a;
}
__device__ __forceinline__ float4 f4scale(float4 a, float s) {
    a.x *= s; a.y *= s; a.z *= s; a.w *= s; return a;
}

// ---------------- 1) masks (nearest downsample of parse maps) ----------------
__global__ void k_masks(const int* __restrict__ fap, const int* __restrict__ fbp) {
    int p = blockIdx.x * 256 + threadIdx.x;
    if (p >= HW) return;
    int y = (p >> 6) << 2, x = (p & 63) << 2;   // src idx = dst*256/64 = dst*4
    int off = y * 256 + x;
    unsigned code = 0;
#pragma unroll
    for (int k = 0; k < 3; k++) {
        g_maskA[k * HW + p] = (fap[(k + 1) * 65536 + off] != 0) ? 1 : 0;
        if (fbp[(k + 1) * 65536 + off] != 0) code |= (1u << k);
    }
    g_codeB[p] = (unsigned char)code;
}

// ---------------- 2) per-channel spatial means ----------------
__global__ void k_mean(const float* __restrict__ fa, const float* __restrict__ fb) {
    int cb = blockIdx.x;                 // 0..511
    int ch = cb & 255;
    const float* src = (cb < 256) ? fa : fb;
    float s = 0.f;
    for (int i = threadIdx.x; i < HW; i += 256) s += src[ch * HW + i];
    __shared__ float red[256];
    red[threadIdx.x] = s;
    __syncthreads();
    for (int st = 128; st > 0; st >>= 1) {
        if (threadIdx.x < st) red[threadIdx.x] += red[threadIdx.x + st];
        __syncthreads();
    }
    if (threadIdx.x == 0) {
        float m = red[0] / (float)HW;
        if (cb < 256) g_meanA[ch] = m; else g_meanB[ch] = m;
    }
}

// ---------------- 3) center + L2-normalize per position, transpose to [p][c] ----------------
__global__ void k_norm(const float* __restrict__ fa, const float* __restrict__ fb) {
    int p = blockIdx.x * 256 + threadIdx.x;
    if (p >= HW) return;
    const float* src;  const float* mean;  float* dst;
    if (blockIdx.y == 0) { src = fa; mean = g_meanA; dst = g_faT; }
    else                 { src = fb; mean = g_meanB; dst = g_fbT; }
    float nsq = 0.f;
    for (int c = 0; c < CF; c++) {
        float v = src[c * HW + p] - mean[c];
        nsq += v * v;
    }
    float inv = rsqrtf(nsq);
    for (int c = 0; c < CF; c++) {
        float v = src[c * HW + p] - mean[c];
        dst[p * CF + c] = v * inv;
    }
}

// ---------------- 4) bilinear (align_corners) downsample 256->64, store [q][c] ----------------
__global__ void k_ufb(const float* __restrict__ ub) {
    int idx = blockIdx.x * 256 + threadIdx.x;   // q*64 + c
    if (idx >= HW * CO) return;
    int c = idx & 63, q = idx >> 6;
    int i = q >> 6, j = q & 63;
    const float sc = 255.0f / 63.0f;
    float ry = (float)i * sc, rx = (float)j * sc;
    int y0 = (int)ry, x0 = (int)rx;
    int y1 = min(y0 + 1, 255), x1 = min(x0 + 1, 255);
    float wy = ry - (float)y0, wx = rx - (float)x0;
    const float* b = ub + c * 65536;
    float v00 = b[y0 * 256 + x0], v01 = b[y0 * 256 + x1];
    float v10 = b[y1 * 256 + x0], v11 = b[y1 * 256 + x1];
    float r0 = v00 * (1.f - wy) + v10 * wy;
    float r1 = v01 * (1.f - wy) + v11 * wy;
    g_ufb[q * CO + c] = r0 * (1.f - wx) + r1 * wx;
}

// ---------------- 5) U0[c], UB[code][c], counts ----------------
__global__ void k_ub() {
    int c = blockIdx.x;   // 0..63
    __shared__ float s_acc[9];
    __shared__ int   s_cnt[8];
    if (threadIdx.x < 9) s_acc[threadIdx.x] = 0.f;
    if (threadIdx.x < 8) s_cnt[threadIdx.x] = 0;
    __syncthreads();
    float u0 = 0, b0 = 0, b1 = 0, b2 = 0, b3 = 0, b4 = 0, b5 = 0, b6 = 0, b7 = 0;
    int n0 = 0, n1 = 0, n2 = 0, n3 = 0, n4 = 0, n5 = 0, n6 = 0, n7 = 0;
    for (int q = threadIdx.x; q < HW; q += 256) {
        float u = g_ufb[q * CO + c];
        int code = g_codeB[q];
        u0 += u;
        switch (code) {
            case 0: b0 += u; n0++; break;
            case 1: b1 += u; n1++; break;
            case 2: b2 += u; n2++; break;
            case 3: b3 += u; n3++; break;
            case 4: b4 += u; n4++; break;
            case 5: b5 += u; n5++; break;
            case 6: b6 += u; n6++; break;
            case 7: b7 += u; n7++; break;
        }
    }
    atomicAdd(&s_acc[0], u0);
    atomicAdd(&s_acc[1], b0); atomicAdd(&s_acc[2], b1);
    atomicAdd(&s_acc[3], b2); atomicAdd(&s_acc[4], b3);
    atomicAdd(&s_acc[5], b4); atomicAdd(&s_acc[6], b5);
    atomicAdd(&s_acc[7], b6); atomicAdd(&s_acc[8], b7);
    if (c == 0) {
        atomicAdd(&s_cnt[0], n0); atomicAdd(&s_cnt[1], n1);
        atomicAdd(&s_cnt[2], n2); atomicAdd(&s_cnt[3], n3);
        atomicAdd(&s_cnt[4], n4); atomicAdd(&s_cnt[5], n5);
        atomicAdd(&s_cnt[6], n6); atomicAdd(&s_cnt[7], n7);
    }
    __syncthreads();
    if (threadIdx.x == 0) g_U0[c] = s_acc[0];
    if (threadIdx.x < 8) {
        g_UB[threadIdx.x * CO + c] = s_acc[1 + threadIdx.x];
        if (c == 0) g_cnt[threadIdx.x] = (float)s_cnt[threadIdx.x];
    }
}

// ---------------- 6) S-GEMM (NT, fp32) with exp epilogue: X[p][q]=exp(alpha*fa_p.fb_q) ----------------
__global__ void __launch_bounds__(256) k_gemm() {
    __shared__ float As[2][8][128];
    __shared__ float Bs[2][8][128];
    int t = threadIdx.x;
    int tx = t & 15, ty = t >> 4;
    int qb = blockIdx.x << 7, pb = blockIdx.y << 7;
    int m = t >> 1, lk = (t & 1) << 2;
    const float* Ap = g_faT + (size_t)(pb + m) * CF + lk;
    const float* Bp = g_fbT + (size_t)(qb + m) * CF + lk;

    float acc[8][8];
#pragma unroll
    for (int i = 0; i < 8; i++)
#pragma unroll
        for (int j = 0; j < 8; j++) acc[i][j] = 0.f;

    float4 ra = *(const float4*)Ap;
    float4 rb = *(const float4*)Bp;

    for (int k0 = 0; k0 < CF; k0 += 8) {
        int buf = (k0 >> 3) & 1;
        As[buf][lk + 0][m] = ra.x; As[buf][lk + 1][m] = ra.y;
        As[buf][lk + 2][m] = ra.z; As[buf][lk + 3][m] = ra.w;
        Bs[buf][lk + 0][m] = rb.x; Bs[buf][lk + 1][m] = rb.y;
        Bs[buf][lk + 2][m] = rb.z; Bs[buf][lk + 3][m] = rb.w;
        __syncthreads();
        if (k0 + 8 < CF) {
            ra = *(const float4*)(Ap + k0 + 8);
            rb = *(const float4*)(Bp + k0 + 8);
        }
#pragma unroll
        for (int kk = 0; kk < 8; kk++) {
            float a[8], b[8];
            *(float4*)&a[0] = *(const float4*)&As[buf][kk][ty << 3];
            *(float4*)&a[4] = *(const float4*)&As[buf][kk][(ty << 3) + 4];
            *(float4*)&b[0] = *(const float4*)&Bs[buf][kk][tx << 3];
            *(float4*)&b[4] = *(const float4*)&Bs[buf][kk][(tx << 3) + 4];
#pragma unroll
            for (int i = 0; i < 8; i++)
#pragma unroll
                for (int j = 0; j < 8; j++)
                    acc[i][j] += a[i] * b[j];
        }
    }
#pragma unroll
    for (int i = 0; i < 8; i++) {
        float* dst = g_X + (size_t)(pb + (ty << 3) + i) * HW + qb + (tx << 3);
        float4 v0, v1;
        v0.x = expf(fminf(ALPHA * acc[i][0], 80.f));
        v0.y = expf(fminf(ALPHA * acc[i][1], 80.f));
        v0.z = expf(fminf(ALPHA * acc[i][2], 80.f));
        v0.w = expf(fminf(ALPHA * acc[i][3], 80.f));
        v1.x = expf(fminf(ALPHA * acc[i][4], 80.f));
        v1.y = expf(fminf(ALPHA * acc[i][5], 80.f));
        v1.z = expf(fminf(ALPHA * acc[i][6], 80.f));
        v1.w = expf(fminf(ALPHA * acc[i][7], 80.f));
        *(float4*)dst = v0;
        *(float4*)(dst + 4) = v1;
    }
}

// ---------------- 7) H[code][p] = sum_{q:code} X[p][q] (codes 1..7) ----------------
__global__ void k_H() {
    int p = blockIdx.x;
    const float* row = g_X + (size_t)p * HW;
    __shared__ float s_h[8];
    if (threadIdx.x < 8) s_h[threadIdx.x] = 0.f;
    __syncthreads();
    float h1 = 0, h2 = 0, h3 = 0, h4 = 0, h5 = 0, h6 = 0, h7 = 0;
    for (int q = threadIdx.x; q < HW; q += 256) {
        float x = row[q];
        switch (g_codeB[q]) {
            case 1: h1 += x; break;
            case 2: h2 += x; break;
            case 3: h3 += x; break;
            case 4: h4 += x; break;
            case 5: h5 += x; break;
            case 6: h6 += x; break;
            case 7: h7 += x; break;
            default: break;
        }
    }
    atomicAdd(&s_h[1], h1); atomicAdd(&s_h[2], h2); atomicAdd(&s_h[3], h3);
    atomicAdd(&s_h[4], h4); atomicAdd(&s_h[5], h5); atomicAdd(&s_h[6], h6);
    atomicAdd(&s_h[7], h7);
    __syncthreads();
    if (threadIdx.x >= 1 && threadIdx.x < 8)
        g_H[threadIdx.x * HW + p] = s_h[threadIdx.x];
}

// ---------------- 8) main pass: G[code][c][p] accumulation + combine ----------------
// block = 16 p's; thread (cq = c/4, pi = p index); acc per code in registers.
__global__ void __launch_bounds__(256) k_main() {
    __shared__ float Xs[16 * 128];
    __shared__ float4 Us[128 * 16];
    __shared__ unsigned char Cs[128];
    int t = threadIdx.x;
    int cq = t & 15, pi = t >> 4;
    int pb = blockIdx.x << 4;

    float4 a1 = f4z(), a2 = f4z(), a3 = f4z(), a4 = f4z();
    float4 a5 = f4z(), a6 = f4z(), a7 = f4z();

    for (int q0 = 0; q0 < HW; q0 += 128) {
        for (int i = t; i < 2048; i += 256)
            Xs[i] = g_X[(size_t)(pb + (i >> 7)) * HW + q0 + (i & 127)];
        const float4* src = (const float4*)(g_ufb + (size_t)q0 * CO);
        for (int i = t; i < 2048; i += 256) Us[i] = src[i];
        if (t < 128) Cs[t] = g_codeB[q0 + t];
        __syncthreads();

#pragma unroll 4
        for (int q = 0; q < 128; q++) {
            int code = Cs[q];
            if (code) {
                float xv = Xs[(pi << 7) + q];
                float4 u = Us[(q << 4) + cq];
                switch (code) {
                    case 1: a1.x += u.x*xv; a1.y += u.y*xv; a1.z += u.z*xv; a1.w += u.w*xv; break;
                    case 2: a2.x += u.x*xv; a2.y += u.y*xv; a2.z += u.z*xv; a2.w += u.w*xv; break;
                    case 3: a3.x += u.x*xv; a3.y += u.y*xv; a3.z += u.z*xv; a3.w += u.w*xv; break;
                    case 4: a4.x += u.x*xv; a4.y += u.y*xv; a4.z += u.z*xv; a4.w += u.w*xv; break;
                    case 5: a5.x += u.x*xv; a5.y += u.y*xv; a5.z += u.z*xv; a5.w += u.w*xv; break;
                    case 6: a6.x += u.x*xv; a6.y += u.y*xv; a6.z += u.z*xv; a6.w += u.w*xv; break;
                    default:a7.x += u.x*xv; a7.y += u.y*xv; a7.z += u.z*xv; a7.w += u.w*xv; break;
                }
            }
        }
        __syncthreads();
    }

    // combine epilogue
    int p = pb + pi;
    const float4* UB4 = (const float4*)g_UB;   // index: code*16 + cq
    float4 u0 = ((const float4*)g_U0)[cq];
    float4 comb = f4z();
    float msum = 0.f;

    // k=0 : codes {1,3,5,7}
    if (g_maskA[p]) {
        msum += 1.f;
        float E  = g_H[1 * HW + p] + g_H[3 * HW + p] + g_H[5 * HW + p] + g_H[7 * HW + p];
        float nb = g_cnt[1] + g_cnt[3] + g_cnt[5] + g_cnt[7];
        float4 B  = f4add(f4add(UB4[1 * 16 + cq], UB4[3 * 16 + cq]),
                          f4add(UB4[5 * 16 + cq], UB4[7 * 16 + cq]));
        float4 w1 = f4add(f4add(a1, a3), f4add(a5, a7));
        float inv = 1.0f / (E + (4096.0f - nb));
        comb = f4add(comb, f4scale(f4sub(f4add(w1, u0), B), inv));
    }
    // k=1 : codes {2,3,6,7}
    if (g_maskA[HW + p]) {
        msum += 1.f;
        float E  = g_H[2 * HW + p] + g_H[3 * HW + p] + g_H[6 * HW + p] + g_H[7 * HW + p];
        float nb = g_cnt[2] + g_cnt[3] + g_cnt[6] + g_cnt[7];
        float4 B  = f4add(f4add(UB4[2 * 16 + cq], UB4[3 * 16 + cq]),
                          f4add(UB4[6 * 16 + cq], UB4[7 * 16 + cq]));
        float4 w1 = f4add(f4add(a2, a3), f4add(a6, a7));
        float inv = 1.0f / (E + (4096.0f - nb));
        comb = f4add(comb, f4scale(f4sub(f4add(w1, u0), B), inv));
    }
    // k=2 : codes {4,5,6,7}
    if (g_maskA[2 * HW + p]) {
        msum += 1.f;
        float E  = g_H[4 * HW + p] + g_H[5 * HW + p] + g_H[6 * HW + p] + g_H[7 * HW + p];
        float nb = g_cnt[4] + g_cnt[5] + g_cnt[6] + g_cnt[7];
        float4 B  = f4add(f4add(UB4[4 * 16 + cq], UB4[5 * 16 + cq]),
                          f4add(UB4[6 * 16 + cq], UB4[7 * 16 + cq]));
        float4 w1 = f4add(f4add(a4, a5), f4add(a6, a7));
        float inv = 1.0f / (E + (4096.0f - nb));
        comb = f4add(comb, f4scale(f4sub(f4add(w1, u0), B), inv));
    }

    float dn = fmaxf(msum, 1.0f);
    float4 res = f4scale(comb, 1.0f / dn);
    ((float4*)g_aligned)[(p << 4) + cq] = res;
}

// ---------------- 9) bilinear (align_corners) upsample 64 -> 256 ----------------
__global__ void k_up(float* __restrict__ out) {
    int idx = blockIdx.x * 256 + threadIdx.x;    // c*65536 + Y*256 + X
    if (idx >= CO * 65536) return;
    int c = idx >> 16, Y = (idx >> 8) & 255, X = idx & 255;
    const float sc = 63.0f / 255.0f;
    float ry = (float)Y * sc, rx = (float)X * sc;
    int y0 = (int)ry, x0 = (int)rx;
    int y1 = min(y0 + 1, 63), x1 = min(x0 + 1, 63);
    float wy = ry - (float)y0, wx = rx - (float)x0;
    const float* A = g_aligned;
    float v00 = A[((y0 << 6) + x0) * CO + c];
    float v01 = A[((y0 << 6) + x1) * CO + c];
    float v10 = A[((y1 << 6) + x0) * CO + c];
    float v11 = A[((y1 << 6) + x1) * CO + c];
    float r0 = v00 * (1.f - wy) + v10 * wy;
    float r1 = v01 * (1.f - wy) + v11 * wy;
    out[idx] = r0 * (1.f - wx) + r1 * wx;
}

// ---------------- launch ----------------
extern "C" void kernel_launch(void* const* d_in, const int* in_sizes, int n_in,
                              void* d_out, int out_size) {
    const float* ufb_in = (const float*)d_in[0];   // (1,64,256,256)
    const float* fa     = (const float*)d_in[1];   // (1,256,64,64)
    const int*   fap    = (const int*)  d_in[2];   // (1,4,256,256)
    const float* fb     = (const float*)d_in[3];   // (1,256,64,64)
    const int*   fbp    = (const int*)  d_in[4];   // (1,4,256,256)
    float* out = (float*)d_out;                    // (1,64,256,256)

    k_masks<<<16, 256>>>(fap, fbp);
    k_mean<<<512, 256>>>(fa, fb);
    k_norm<<<dim3(16, 2), 256>>>(fa, fb);
    k_ufb<<<(HW * CO) / 256, 256>>>(ufb_in);
    k_ub<<<64, 256>>>();
    k_gemm<<<dim3(32, 32), 256>>>();
    k_H<<<HW, 256>>>();
    k_main<<<HW / 16, 256>>>();
    k_up<<<(CO * 65536) / 256, 256>>>(out);
}

// round 3
// speedup vs baseline: 1.5280x; 1.5280x over previous
#include <cuda_runtime.h>
#include <cuda_bf16.h>
#include <math.h>
#include <stdint.h>

#define HW 4096         // 64*64 spatial positions at feature res
#define CF 256          // feature channels
#define CO 64           // value channels (unalign_fb)
#define ALPHA 100.0f
#define QTILES 32       // HW/128

// ---------------- device scratch (allocation-free) ----------------
__device__ float g_X[(size_t)HW * HW];    // X[p][q] = exp(alpha * S[q,p]), 64 MB
__device__ float g_faT[HW * CF];          // normalized fa, [p][c]
__device__ float g_fbT[HW * CF];          // normalized fb, [q][c]
__device__ __nv_bfloat16 g_faHi[HW * CF];
__device__ __nv_bfloat16 g_faLo[HW * CF];
__device__ __nv_bfloat16 g_fbHi[HW * CF];
__device__ __nv_bfloat16 g_fbLo[HW * CF];
__device__ float g_ufb[HW * CO];          // downsampled values, [q][c]
__device__ float g_meanA[CF];
__device__ float g_meanB[CF];
__device__ unsigned char g_maskA[3 * HW];
__device__ unsigned char g_codeB[HW];     // 3-bit code of mask_b per q
__device__ float g_Hpart[QTILES * 8 * HW];// per-qtile per-code partial sums
__device__ float g_H[8 * HW];             // H[code][p] = sum_{q:code} X[p][q]
__device__ float g_U0[CO];                // sum_q ufb[q][c]
__device__ float g_UB[8 * CO];            // UB[code][c]
__device__ float g_cnt[8];                // count of q per code
__device__ float g_aligned[HW * CO];      // [p][c]

// ---------------- helpers ----------------
__device__ __forceinline__ uint32_t smem_u32(const void* p) {
    uint32_t a;
    asm("{ .reg .u64 t; cvta.to.shared.u64 t, %1; cvt.u32.u64 %0, t; }" : "=r"(a) : "l"(p));
    return a;
}

#define LDSM_X4(r0, r1, r2, r3, addr) \
    asm volatile("ldmatrix.sync.aligned.m8n8.x4.shared.b16 {%0,%1,%2,%3}, [%4];" \
        : "=r"(r0), "=r"(r1), "=r"(r2), "=r"(r3) : "r"(addr))

__device__ __forceinline__ void mma_bf16(float* c, const uint32_t* a, uint32_t b0, uint32_t b1) {
    asm volatile(
        "mma.sync.aligned.m16n8k16.row.col.f32.bf16.bf16.f32 "
        "{%0,%1,%2,%3}, {%4,%5,%6,%7}, {%8,%9}, {%0,%1,%2,%3};"
        : "+f"(c[0]), "+f"(c[1]), "+f"(c[2]), "+f"(c[3])
        : "r"(a[0]), "r"(a[1]), "r"(a[2]), "r"(a[3]), "r"(b0), "r"(b1));
}

__device__ __forceinline__ float4 f4z() { return make_float4(0.f, 0.f, 0.f, 0.f); }
__device__ __forceinline__ float4 f4add(float4 a, float4 b) {
    a.x += b.x; a.y += b.y; a.z += b.z; a.w += b.w; return a;
}
__device__ __forceinline__ float4 f4sub(float4 a, float4 b) {
    a.x -= b.x; a.y -= b.y; a.z -= b.z; a.w -= b.w; return a;
}
__device__ __forceinline__ float4 f4scale(float4 a, float s) {
    a.x *= s; a.y *= s; a.z *= s; a.w *= s; return a;
}

// ---------------- 1) masks ----------------
__global__ void k_masks(const int* __restrict__ fap, const int* __restrict__ fbp) {
    int p = blockIdx.x * 256 + threadIdx.x;
    if (p >= HW) return;
    int y = (p >> 6) << 2, x = (p & 63) << 2;
    int off = y * 256 + x;
    unsigned code = 0;
#pragma unroll
    for (int k = 0; k < 3; k++) {
        g_maskA[k * HW + p] = (fap[(k + 1) * 65536 + off] != 0) ? 1 : 0;
        if (fbp[(k + 1) * 65536 + off] != 0) code |= (1u << k);
    }
    g_codeB[p] = (unsigned char)code;
}

// ---------------- 2) per-channel spatial means ----------------
__global__ void k_mean(const float* __restrict__ fa, const float* __restrict__ fb) {
    int cb = blockIdx.x;
    int ch = cb & 255;
    const float* src = (cb < 256) ? fa : fb;
    float s = 0.f;
    for (int i = threadIdx.x; i < HW; i += 256) s += src[ch * HW + i];
    __shared__ float red[256];
    red[threadIdx.x] = s;
    __syncthreads();
    for (int st = 128; st > 0; st >>= 1) {
        if (threadIdx.x < st) red[threadIdx.x] += red[threadIdx.x + st];
        __syncthreads();
    }
    if (threadIdx.x == 0) {
        float m = red[0] / (float)HW;
        if (cb < 256) g_meanA[ch] = m; else g_meanB[ch] = m;
    }
}

// ---------------- 3) center + normalize, transpose to [p][c] ----------------
__global__ void k_norm(const float* __restrict__ fa, const float* __restrict__ fb) {
    int p = blockIdx.x * 256 + threadIdx.x;
    if (p >= HW) return;
    const float* src;  const float* mean;  float* dst;
    if (blockIdx.y == 0) { src = fa; mean = g_meanA; dst = g_faT; }
    else                 { src = fb; mean = g_meanB; dst = g_fbT; }
    float nsq = 0.f;
    for (int c = 0; c < CF; c++) {
        float v = src[c * HW + p] - mean[c];
        nsq += v * v;
    }
    float inv = rsqrtf(nsq);
    for (int c = 0; c < CF; c++) {
        float v = src[c * HW + p] - mean[c];
        dst[p * CF + c] = v * inv;
    }
}

// ---------------- 3b) bf16 hi/lo split ----------------
__global__ void k_split() {
    int i = blockIdx.x * 256 + threadIdx.x;
    if (i >= HW * CF) return;
    float va = g_faT[i];
    __nv_bfloat16 ha = __float2bfloat16(va);
    g_faHi[i] = ha;
    g_faLo[i] = __float2bfloat16(va - __bfloat162float(ha));
    float vb = g_fbT[i];
    __nv_bfloat16 hb = __float2bfloat16(vb);
    g_fbHi[i] = hb;
    g_fbLo[i] = __float2bfloat16(vb - __bfloat162float(hb));
}

// ---------------- 4) bilinear downsample 256->64, store [q][c] ----------------
__global__ void k_ufb(const float* __restrict__ ub) {
    int idx = blockIdx.x * 256 + threadIdx.x;
    if (idx >= HW * CO) return;
    int c = idx & 63, q = idx >> 6;
    int i = q >> 6, j = q & 63;
    const float sc = 255.0f / 63.0f;
    float ry = (float)i * sc, rx = (float)j * sc;
    int y0 = (int)ry, x0 = (int)rx;
    int y1 = min(y0 + 1, 255), x1 = min(x0 + 1, 255);
    float wy = ry - (float)y0, wx = rx - (float)x0;
    const float* b = ub + c * 65536;
    float v00 = b[y0 * 256 + x0], v01 = b[y0 * 256 + x1];
    float v10 = b[y1 * 256 + x0], v11 = b[y1 * 256 + x1];
    float r0 = v00 * (1.f - wy) + v10 * wy;
    float r1 = v01 * (1.f - wy) + v11 * wy;
    g_ufb[q * CO + c] = r0 * (1.f - wx) + r1 * wx;
}

// ---------------- 5) U0[c], UB[code][c], counts ----------------
__global__ void k_ub() {
    int c = blockIdx.x;
    __shared__ float s_acc[9];
    __shared__ int   s_cnt[8];
    if (threadIdx.x < 9) s_acc[threadIdx.x] = 0.f;
    if (threadIdx.x < 8) s_cnt[threadIdx.x] = 0;
    __syncthreads();
    float acc[9] = {0,0,0,0,0,0,0,0,0};
    int cnt[8] = {0,0,0,0,0,0,0,0};
    for (int q = threadIdx.x; q < HW; q += 256) {
        float u = g_ufb[q * CO + c];
        int code = g_codeB[q];
        acc[0] += u;
        acc[1 + code] += u;
        cnt[code]++;
    }
#pragma unroll
    for (int i = 0; i < 9; i++) atomicAdd(&s_acc[i], acc[i]);
    if (c == 0)
#pragma unroll
        for (int i = 0; i < 8; i++) atomicAdd(&s_cnt[i], cnt[i]);
    __syncthreads();
    if (threadIdx.x == 0) g_U0[c] = s_acc[0];
    if (threadIdx.x < 8) {
        g_UB[threadIdx.x * CO + c] = s_acc[1 + threadIdx.x];
        if (c == 0) g_cnt[threadIdx.x] = (float)s_cnt[threadIdx.x];
    }
}

// ---------------- 6) mma.sync split-bf16 S-GEMM + exp + H-partials ----------------
// CTA: 256 threads = 8 warps, 4x2 warp grid; each warp: 32(m) x 64(n).
// smem tiles: [128 rows][40 bf16] padded (80B stride -> conflict-free ldmatrix).
#define SROW 40

__global__ void __launch_bounds__(256, 2) k_gemm_mma() {
    __shared__ __nv_bfloat16 sA[2][128][SROW];   // [hi/lo][row p][k]
    __shared__ __nv_bfloat16 sB[2][128][SROW];   // [hi/lo][row q][k]
    __shared__ float h_s[128][8];
    __shared__ unsigned char s_codes[128];

    int t = threadIdx.x, w = t >> 5, l = t & 31;
    int qb = blockIdx.x << 7, pb = blockIdx.y << 7;
    int wm = w >> 1, wn = w & 1;

    for (int i = t; i < 1024; i += 256) ((float*)h_s)[i] = 0.f;
    if (t < 128) s_codes[t] = g_codeB[qb + t];

    float acc[2][8][4];
#pragma unroll
    for (int a = 0; a < 2; a++)
#pragma unroll
        for (int b = 0; b < 8; b++)
#pragma unroll
            for (int cc = 0; cc < 4; cc++) acc[a][b][cc] = 0.f;

    uint32_t sbA = smem_u32(&sA[0][0][0]);
    uint32_t sbB = smem_u32(&sB[0][0][0]);
    const uint32_t LO_OFF = 128 * SROW * 2;   // bytes from hi to lo plane

    int rowA = wm * 32 + (l & 15);
    int rowB = wn * 64 + (l & 15);
    uint32_t colb = (uint32_t)((l >> 4) << 4);  // k-half byte offset

    int r = t >> 2, seg = t & 3;                // global->smem mapping (2 iters)
    int r2 = (t + 256) >> 2, seg2 = (t + 256) & 3;

    for (int kc = 0; kc < 8; kc++) {
        // ---- load 32-wide k chunk of all 4 operand planes ----
        int kof = kc * 32;
        *(int4*)&sA[0][r][seg * 8]   = *(const int4*)&g_faHi[(size_t)(pb + r) * CF + kof + seg * 8];
        *(int4*)&sA[1][r][seg * 8]   = *(const int4*)&g_faLo[(size_t)(pb + r) * CF + kof + seg * 8];
        *(int4*)&sB[0][r][seg * 8]   = *(const int4*)&g_fbHi[(size_t)(qb + r) * CF + kof + seg * 8];
        *(int4*)&sB[1][r][seg * 8]   = *(const int4*)&g_fbLo[(size_t)(qb + r) * CF + kof + seg * 8];
        *(int4*)&sA[0][r2][seg2 * 8] = *(const int4*)&g_faHi[(size_t)(pb + r2) * CF + kof + seg2 * 8];
        *(int4*)&sA[1][r2][seg2 * 8] = *(const int4*)&g_faLo[(size_t)(pb + r2) * CF + kof + seg2 * 8];
        *(int4*)&sB[0][r2][seg2 * 8] = *(const int4*)&g_fbHi[(size_t)(qb + r2) * CF + kof + seg2 * 8];
        *(int4*)&sB[1][r2][seg2 * 8] = *(const int4*)&g_fbLo[(size_t)(qb + r2) * CF + kof + seg2 * 8];
        __syncthreads();

#pragma unroll
        for (int kk2 = 0; kk2 < 2; kk2++) {
            uint32_t kb = (uint32_t)(kk2 * 32) + colb;   // byte offset within row
            uint32_t ah[2][4], al[2][4];
#pragma unroll
            for (int mi = 0; mi < 2; mi++) {
                uint32_t ad = sbA + (uint32_t)((rowA + mi * 16) * (SROW * 2)) + kb;
                LDSM_X4(ah[mi][0], ah[mi][1], ah[mi][2], ah[mi][3], ad);
                LDSM_X4(al[mi][0], al[mi][1], al[mi][2], al[mi][3], ad + LO_OFF);
            }
#pragma unroll
            for (int np = 0; np < 4; np++) {
                uint32_t bd = sbB + (uint32_t)((rowB + np * 16) * (SROW * 2)) + kb;
                uint32_t bh[4], bl[4];
                LDSM_X4(bh[0], bh[1], bh[2], bh[3], bd);
                LDSM_X4(bl[0], bl[1], bl[2], bl[3], bd + LO_OFF);
#pragma unroll
                for (int mi = 0; mi < 2; mi++) {
                    mma_bf16(acc[mi][np * 2 + 0], ah[mi], bh[0], bh[2]);
                    mma_bf16(acc[mi][np * 2 + 0], ah[mi], bl[0], bl[2]);
                    mma_bf16(acc[mi][np * 2 + 0], al[mi], bh[0], bh[2]);
                    mma_bf16(acc[mi][np * 2 + 1], ah[mi], bh[1], bh[3]);
                    mma_bf16(acc[mi][np * 2 + 1], ah[mi], bl[1], bl[3]);
                    mma_bf16(acc[mi][np * 2 + 1], al[mi], bh[1], bh[3]);
                }
            }
        }
        __syncthreads();
    }

    // ---- epilogue: exp, X store, per-code H partials ----
    int prl = wm * 32 + (l >> 2);          // local p row (base)
    int qcl = wn * 64 + (l & 3) * 2;       // local q col (base)
#pragma unroll
    for (int mi = 0; mi < 2; mi++) {
#pragma unroll
        for (int nj = 0; nj < 8; nj++) {
#pragma unroll
            for (int half = 0; half < 2; half++) {
                int rloc = prl + mi * 16 + half * 8;
                int qloc = qcl + nj * 8;
                float x0 = __expf(fminf(ALPHA * acc[mi][nj][half * 2 + 0], 80.f));
                float x1 = __expf(fminf(ALPHA * acc[mi][nj][half * 2 + 1], 80.f));
                int c0 = s_codes[qloc], c1 = s_codes[qloc + 1];
                if (c0) atomicAdd(&h_s[rloc][c0], x0);
                if (c1) atomicAdd(&h_s[rloc][c1], x1);
                *(float2*)&g_X[(size_t)(pb + rloc) * HW + qb + qloc] = make_float2(x0, x1);
            }
        }
    }
    __syncthreads();
    float* hp = g_Hpart + (size_t)blockIdx.x * 8 * HW;
    for (int i = t; i < 128 * 7; i += 256) {
        int p = i & 127, code = (i >> 7) + 1;
        hp[code * HW + pb + p] = h_s[p][code];
    }
}

// ---------------- 6b) reduce H partials ----------------
__global__ void k_Hred() {
    int idx = blockIdx.x * 256 + threadIdx.x;   // (code-1)*HW + p, 7*HW total
    if (idx >= 7 * HW) return;
    int code = idx / HW + 1;
    int p = idx % HW;
    float s = 0.f;
    for (int t = 0; t < QTILES; t++)
        s += g_Hpart[(size_t)t * 8 * HW + code * HW + p];
    g_H[code * HW + p] = s;
}

// ---------------- 8) main pass: code-routed value accumulation + combine ----------------
__global__ void __launch_bounds__(256) k_main() {
    __shared__ float Xs[16 * 128];
    __shared__ float4 Us[128 * 16];
    __shared__ unsigned char Cs[128];
    int t = threadIdx.x;
    int cq = t & 15, pi = t >> 4;
    int pb = blockIdx.x << 4;

    float4 a1 = f4z(), a2 = f4z(), a3 = f4z(), a4 = f4z();
    float4 a5 = f4z(), a6 = f4z(), a7 = f4z();

    for (int q0 = 0; q0 < HW; q0 += 128) {
        for (int i = t; i < 2048; i += 256)
            Xs[i] = g_X[(size_t)(pb + (i >> 7)) * HW + q0 + (i & 127)];
        const float4* src = (const float4*)(g_ufb + (size_t)q0 * CO);
        for (int i = t; i < 2048; i += 256) Us[i] = src[i];
        if (t < 128) Cs[t] = g_codeB[q0 + t];
        __syncthreads();

#pragma unroll 4
        for (int q = 0; q < 128; q++) {
            int code = Cs[q];
            if (code) {
                float xv = Xs[(pi << 7) + q];
                float4 u = Us[(q << 4) + cq];
                switch (code) {
                    case 1: a1.x += u.x*xv; a1.y += u.y*xv; a1.z += u.z*xv; a1.w += u.w*xv; break;
                    case 2: a2.x += u.x*xv; a2.y += u.y*xv; a2.z += u.z*xv; a2.w += u.w*xv; break;
                    case 3: a3.x += u.x*xv; a3.y += u.y*xv; a3.z += u.z*xv; a3.w += u.w*xv; break;
                    case 4: a4.x += u.x*xv; a4.y += u.y*xv; a4.z += u.z*xv; a4.w += u.w*xv; break;
                    case 5: a5.x += u.x*xv; a5.y += u.y*xv; a5.z += u.z*xv; a5.w += u.w*xv; break;
                    case 6: a6.x += u.x*xv; a6.y += u.y*xv; a6.z += u.z*xv; a6.w += u.w*xv; break;
                    default:a7.x += u.x*xv; a7.y += u.y*xv; a7.z += u.z*xv; a7.w += u.w*xv; break;
                }
            }
        }
        __syncthreads();
    }

    int p = pb + pi;
    const float4* UB4 = (const float4*)g_UB;
    float4 u0 = ((const float4*)g_U0)[cq];
    float4 comb = f4z();
    float msum = 0.f;

    if (g_maskA[p]) {
        msum += 1.f;
        float E  = g_H[1 * HW + p] + g_H[3 * HW + p] + g_H[5 * HW + p] + g_H[7 * HW + p];
        float nb = g_cnt[1] + g_cnt[3] + g_cnt[5] + g_cnt[7];
        float4 B  = f4add(f4add(UB4[1 * 16 + cq], UB4[3 * 16 + cq]),
                          f4add(UB4[5 * 16 + cq], UB4[7 * 16 + cq]));
        float4 w1 = f4add(f4add(a1, a3), f4add(a5, a7));
        float inv = 1.0f / (E + (4096.0f - nb));
        comb = f4add(comb, f4scale(f4sub(f4add(w1, u0), B), inv));
    }
    if (g_maskA[HW + p]) {
        msum += 1.f;
        float E  = g_H[2 * HW + p] + g_H[3 * HW + p] + g_H[6 * HW + p] + g_H[7 * HW + p];
        float nb = g_cnt[2] + g_cnt[3] + g_cnt[6] + g_cnt[7];
        float4 B  = f4add(f4add(UB4[2 * 16 + cq], UB4[3 * 16 + cq]),
                          f4add(UB4[6 * 16 + cq], UB4[7 * 16 + cq]));
        float4 w1 = f4add(f4add(a2, a3), f4add(a6, a7));
        float inv = 1.0f / (E + (4096.0f - nb));
        comb = f4add(comb, f4scale(f4sub(f4add(w1, u0), B), inv));
    }
    if (g_maskA[2 * HW + p]) {
        msum += 1.f;
        float E  = g_H[4 * HW + p] + g_H[5 * HW + p] + g_H[6 * HW + p] + g_H[7 * HW + p];
        float nb = g_cnt[4] + g_cnt[5] + g_cnt[6] + g_cnt[7];
        float4 B  = f4add(f4add(UB4[4 * 16 + cq], UB4[5 * 16 + cq]),
                          f4add(UB4[6 * 16 + cq], UB4[7 * 16 + cq]));
        float4 w1 = f4add(f4add(a4, a5), f4add(a6, a7));
        float inv = 1.0f / (E + (4096.0f - nb));
        comb = f4add(comb, f4scale(f4sub(f4add(w1, u0), B), inv));
    }

    float dn = fmaxf(msum, 1.0f);
    float4 res = f4scale(comb, 1.0f / dn);
    ((float4*)g_aligned)[(p << 4) + cq] = res;
}

// ---------------- 9) bilinear upsample 64 -> 256 ----------------
__global__ void k_up(float* __restrict__ out) {
    int idx = blockIdx.x * 256 + threadIdx.x;
    if (idx >= CO * 65536) return;
    int c = idx >> 16, Y = (idx >> 8) & 255, X = idx & 255;
    const float sc = 63.0f / 255.0f;
    float ry = (float)Y * sc, rx = (float)X * sc;
    int y0 = (int)ry, x0 = (int)rx;
    int y1 = min(y0 + 1, 63), x1 = min(x0 + 1, 63);
    float wy = ry - (float)y0, wx = rx - (float)x0;
    const float* A = g_aligned;
    float v00 = A[((y0 << 6) + x0) * CO + c];
    float v01 = A[((y0 << 6) + x1) * CO + c];
    float v10 = A[((y1 << 6) + x0) * CO + c];
    float v11 = A[((y1 << 6) + x1) * CO + c];
    float r0 = v00 * (1.f - wy) + v10 * wy;
    float r1 = v01 * (1.f - wy) + v11 * wy;
    out[idx] = r0 * (1.f - wx) + r1 * wx;
}

// ---------------- launch ----------------
extern "C" void kernel_launch(void* const* d_in, const int* in_sizes, int n_in,
                              void* d_out, int out_size) {
    const float* ufb_in = (const float*)d_in[0];   // (1,64,256,256)
    const float* fa     = (const float*)d_in[1];   // (1,256,64,64)
    const int*   fap    = (const int*)  d_in[2];   // (1,4,256,256)
    const float* fb     = (const float*)d_in[3];   // (1,256,64,64)
    const int*   fbp    = (const int*)  d_in[4];   // (1,4,256,256)
    float* out = (float*)d_out;                    // (1,64,256,256)

    k_masks<<<16, 256>>>(fap, fbp);
    k_mean<<<512, 256>>>(fa, fb);
    k_norm<<<dim3(16, 2), 256>>>(fa, fb);
    k_split<<<HW * CF / 256, 256>>>();
    k_ufb<<<(HW * CO) / 256, 256>>>(ufb_in);
    k_ub<<<64, 256>>>();
    k_gemm_mma<<<dim3(32, 32), 256>>>();
    k_Hred<<<(7 * HW + 255) / 256, 256>>>();
    k_main<<<HW / 16, 256>>>();
    k_up<<<(CO * 65536) / 256, 256>>>(out);
}

// round 4
// speedup vs baseline: 1.7905x; 1.1718x over previous
#include <cuda_runtime.h>
#include <cuda_bf16.h>
#include <math.h>
#include <stdint.h>

#define HW 4096         // 64*64 spatial positions at feature res
#define CF 256          // feature channels
#define CO 64           // value channels (unalign_fb)
#define ALPHA 100.0f
#define NV 208          // GEMM2 output cols: 3*64 warped + 3 E + 13 pad

// ---------------- device scratch (allocation-free) ----------------
__device__ uint2 g_Xil[(size_t)HW * HW / 2]; // interleaved: .x = bf16x2 hi(q,q+1), .y = lo
__device__ __nv_bfloat16 g_faHi[HW * CF];
__device__ __nv_bfloat16 g_faLo[HW * CF];
__device__ __nv_bfloat16 g_fbHi[HW * CF];
__device__ __nv_bfloat16 g_fbLo[HW * CF];
__device__ __nv_bfloat16 g_Vthi[NV * HW];    // V^T [col][q]
__device__ __nv_bfloat16 g_Vtlo[NV * HW];
__device__ float g_Wpart[8 * HW * NV];       // GEMM2 k-split partials
__device__ float g_W[HW * NV];
__device__ float g_ufb[HW * CO];             // downsampled values, [q][c]
__device__ float g_meanA[CF];
__device__ float g_meanB[CF];
__device__ unsigned char g_maskA[3 * HW];
__device__ unsigned char g_codeB[HW];        // 3-bit code of mask_b per q
__device__ float g_U0[CO];                   // sum_q ufb[q][c]
__device__ float g_Bk[3 * CO];               // B_k[c] = sum_{q in mb_k} ufb[q][c]
__device__ float g_nbk[3];                   // |mb_k|
__device__ float g_aligned[HW * CO];         // [p][c]

// ---------------- helpers ----------------
__device__ __forceinline__ uint32_t smem_u32(const void* p) {
    uint32_t a;
    asm("{ .reg .u64 t; cvta.to.shared.u64 t, %1; cvt.u32.u64 %0, t; }" : "=r"(a) : "l"(p));
    return a;
}

#define LDSM_X4(r0, r1, r2, r3, addr) \
    asm volatile("ldmatrix.sync.aligned.m8n8.x4.shared.b16 {%0,%1,%2,%3}, [%4];" \
        : "=r"(r0), "=r"(r1), "=r"(r2), "=r"(r3) : "r"(addr))

__device__ __forceinline__ void mma_bf16(float* c, const uint32_t* a, uint32_t b0, uint32_t b1) {
    asm volatile(
        "mma.sync.aligned.m16n8k16.row.col.f32.bf16.bf16.f32 "
        "{%0,%1,%2,%3}, {%4,%5,%6,%7}, {%8,%9}, {%0,%1,%2,%3};"
        : "+f"(c[0]), "+f"(c[1]), "+f"(c[2]), "+f"(c[3])
        : "r"(a[0]), "r"(a[1]), "r"(a[2]), "r"(a[3]), "r"(b0), "r"(b1));
}

// ---------------- 1) masks ----------------
__global__ void k_masks(const int* __restrict__ fap, const int* __restrict__ fbp) {
    int p = blockIdx.x * 256 + threadIdx.x;
    if (p >= HW) return;
    int y = (p >> 6) << 2, x = (p & 63) << 2;
    int off = y * 256 + x;
    unsigned code = 0;
#pragma unroll
    for (int k = 0; k < 3; k++) {
        g_maskA[k * HW + p] = (fap[(k + 1) * 65536 + off] != 0) ? 1 : 0;
        if (fbp[(k + 1) * 65536 + off] != 0) code |= (1u << k);
    }
    g_codeB[p] = (unsigned char)code;
}

// ---------------- 2) per-channel spatial means ----------------
__global__ void k_mean(const float* __restrict__ fa, const float* __restrict__ fb) {
    int cb = blockIdx.x;
    int ch = cb & 255;
    const float* src = (cb < 256) ? fa : fb;
    float s = 0.f;
    for (int i = threadIdx.x; i < HW; i += 256) s += src[ch * HW + i];
    __shared__ float red[256];
    red[threadIdx.x] = s;
    __syncthreads();
    for (int st = 128; st > 0; st >>= 1) {
        if (threadIdx.x < st) red[threadIdx.x] += red[threadIdx.x + st];
        __syncthreads();
    }
    if (threadIdx.x == 0) {
        float m = red[0] / (float)HW;
        if (cb < 256) g_meanA[ch] = m; else g_meanB[ch] = m;
    }
}

// ---------------- 3) center + normalize + bf16 hi/lo split, transpose to [p][c] ----------------
__global__ void k_norm(const float* __restrict__ fa, const float* __restrict__ fb) {
    int p = blockIdx.x * 256 + threadIdx.x;
    if (p >= HW) return;
    const float* src;  const float* mean;
    __nv_bfloat16 *dHi, *dLo;
    if (blockIdx.y == 0) { src = fa; mean = g_meanA; dHi = g_faHi; dLo = g_faLo; }
    else                 { src = fb; mean = g_meanB; dHi = g_fbHi; dLo = g_fbLo; }
    float nsq = 0.f;
    for (int c = 0; c < CF; c++) {
        float v = src[c * HW + p] - mean[c];
        nsq += v * v;
    }
    float inv = rsqrtf(nsq);
    for (int c = 0; c < CF; c++) {
        float v = (src[c * HW + p] - mean[c]) * inv;
        __nv_bfloat16 h = __float2bfloat16(v);
        dHi[p * CF + c] = h;
        dLo[p * CF + c] = __float2bfloat16(v - __bfloat162float(h));
    }
}

// ---------------- 4) bilinear downsample 256->64, store [q][c] ----------------
__global__ void k_ufb(const float* __restrict__ ub) {
    int idx = blockIdx.x * 256 + threadIdx.x;
    if (idx >= HW * CO) return;
    int c = idx & 63, q = idx >> 6;
    int i = q >> 6, j = q & 63;
    const float sc = 255.0f / 63.0f;
    float ry = (float)i * sc, rx = (float)j * sc;
    int y0 = (int)ry, x0 = (int)rx;
    int y1 = min(y0 + 1, 255), x1 = min(x0 + 1, 255);
    float wy = ry - (float)y0, wx = rx - (float)x0;
    const float* b = ub + c * 65536;
    float v00 = b[y0 * 256 + x0], v01 = b[y0 * 256 + x1];
    float v10 = b[y1 * 256 + x0], v11 = b[y1 * 256 + x1];
    float r0 = v00 * (1.f - wy) + v10 * wy;
    float r1 = v01 * (1.f - wy) + v11 * wy;
    g_ufb[q * CO + c] = r0 * (1.f - wx) + r1 * wx;
}

// ---------------- 5) U0[c], Bk[k][c], nbk ----------------
__global__ void k_ub() {
    int c = blockIdx.x;   // 0..63
    __shared__ float s_acc[4];
    __shared__ int   s_n[3];
    if (threadIdx.x < 4) s_acc[threadIdx.x] = 0.f;
    if (threadIdx.x < 3) s_n[threadIdx.x] = 0;
    __syncthreads();
    float a0 = 0, b0 = 0, b1 = 0, b2 = 0;
    int n0 = 0, n1 = 0, n2 = 0;
    for (int q = threadIdx.x; q < HW; q += 256) {
        float u = g_ufb[q * CO + c];
        int code = g_codeB[q];
        a0 += u;
        if (code & 1) { b0 += u; n0++; }
        if (code & 2) { b1 += u; n1++; }
        if (code & 4) { b2 += u; n2++; }
    }
    atomicAdd(&s_acc[0], a0);
    atomicAdd(&s_acc[1], b0);
    atomicAdd(&s_acc[2], b1);
    atomicAdd(&s_acc[3], b2);
    if (c == 0) {
        atomicAdd(&s_n[0], n0); atomicAdd(&s_n[1], n1); atomicAdd(&s_n[2], n2);
    }
    __syncthreads();
    if (threadIdx.x == 0) g_U0[c] = s_acc[0];
    if (threadIdx.x < 3) {
        g_Bk[threadIdx.x * CO + c] = s_acc[1 + threadIdx.x];
        if (c == 0) g_nbk[threadIdx.x] = (float)s_n[threadIdx.x];
    }
}

// ---------------- 5b) build V^T planes ----------------
__global__ void k_V() {
    int idx = blockIdx.x * 256 + threadIdx.x;   // col*HW + q
    if (idx >= NV * HW) return;
    int col = idx >> 12, q = idx & 4095;
    float v = 0.f;
    int code = g_codeB[q];
    if (col < 192) {
        int k = col >> 6, c = col & 63;
        v = ((code >> k) & 1) ? g_ufb[q * CO + c] : 0.f;
    } else if (col < 195) {
        v = (float)((code >> (col - 192)) & 1);
    }
    __nv_bfloat16 h = __float2bfloat16(v);
    g_Vthi[idx] = h;
    g_Vtlo[idx] = __float2bfloat16(v - __bfloat162float(h));
}

// ---------------- 6) mma.sync split-bf16 S-GEMM + exp + bf16 hi/lo X store ----------------
// CTA: 256 threads = 8 warps, 4x2 warp grid; each warp: 32(m) x 64(n).
#define SROW 40

__global__ void __launch_bounds__(256, 2) k_gemm_mma() {
    __shared__ __nv_bfloat16 sA[2][128][SROW];   // [hi/lo][row p][k]
    __shared__ __nv_bfloat16 sB[2][128][SROW];   // [hi/lo][row q][k]

    int t = threadIdx.x, w = t >> 5, l = t & 31;
    int qb = blockIdx.x << 7, pb = blockIdx.y << 7;
    int wm = w >> 1, wn = w & 1;

    float acc[2][8][4];
#pragma unroll
    for (int a = 0; a < 2; a++)
#pragma unroll
        for (int b = 0; b < 8; b++)
#pragma unroll
            for (int cc = 0; cc < 4; cc++) acc[a][b][cc] = 0.f;

    uint32_t sbA = smem_u32(&sA[0][0][0]);
    uint32_t sbB = smem_u32(&sB[0][0][0]);
    const uint32_t LO_OFF = 128 * SROW * 2;

    int rowA = wm * 32 + (l & 15);
    int rowB = wn * 64 + (l & 15);
    uint32_t colb = (uint32_t)((l >> 4) << 4);

    int r = t >> 2, seg = t & 3;
    int r2 = (t + 256) >> 2, seg2 = (t + 256) & 3;

    for (int kc = 0; kc < 8; kc++) {
        int kof = kc * 32;
        *(int4*)&sA[0][r][seg * 8]   = *(const int4*)&g_faHi[(size_t)(pb + r) * CF + kof + seg * 8];
        *(int4*)&sA[1][r][seg * 8]   = *(const int4*)&g_faLo[(size_t)(pb + r) * CF + kof + seg * 8];
        *(int4*)&sB[0][r][seg * 8]   = *(const int4*)&g_fbHi[(size_t)(qb + r) * CF + kof + seg * 8];
        *(int4*)&sB[1][r][seg * 8]   = *(const int4*)&g_fbLo[(size_t)(qb + r) * CF + kof + seg * 8];
        *(int4*)&sA[0][r2][seg2 * 8] = *(const int4*)&g_faHi[(size_t)(pb + r2) * CF + kof + seg2 * 8];
        *(int4*)&sA[1][r2][seg2 * 8] = *(const int4*)&g_faLo[(size_t)(pb + r2) * CF + kof + seg2 * 8];
        *(int4*)&sB[0][r2][seg2 * 8] = *(const int4*)&g_fbHi[(size_t)(qb + r2) * CF + kof + seg2 * 8];
        *(int4*)&sB[1][r2][seg2 * 8] = *(const int4*)&g_fbLo[(size_t)(qb + r2) * CF + kof + seg2 * 8];
        __syncthreads();

#pragma unroll
        for (int kk2 = 0; kk2 < 2; kk2++) {
            uint32_t kb = (uint32_t)(kk2 * 32) + colb;
            uint32_t ah[2][4], al[2][4];
#pragma unroll
            for (int mi = 0; mi < 2; mi++) {
                uint32_t ad = sbA + (uint32_t)((rowA + mi * 16) * (SROW * 2)) + kb;
                LDSM_X4(ah[mi][0], ah[mi][1], ah[mi][2], ah[mi][3], ad);
                LDSM_X4(al[mi][0], al[mi][1], al[mi][2], al[mi][3], ad + LO_OFF);
            }
#pragma unroll
            for (int np = 0; np < 4; np++) {
                uint32_t bd = sbB + (uint32_t)((rowB + np * 16) * (SROW * 2)) + kb;
                uint32_t bh[4], bl[4];
                LDSM_X4(bh[0], bh[1], bh[2], bh[3], bd);
                LDSM_X4(bl[0], bl[1], bl[2], bl[3], bd + LO_OFF);
#pragma unroll
                for (int mi = 0; mi < 2; mi++) {
                    mma_bf16(acc[mi][np * 2 + 0], ah[mi], bh[0], bh[2]);
                    mma_bf16(acc[mi][np * 2 + 0], ah[mi], bl[0], bl[2]);
                    mma_bf16(acc[mi][np * 2 + 0], al[mi], bh[0], bh[2]);
                    mma_bf16(acc[mi][np * 2 + 1], ah[mi], bh[1], bh[3]);
                    mma_bf16(acc[mi][np * 2 + 1], ah[mi], bl[1], bl[3]);
                    mma_bf16(acc[mi][np * 2 + 1], al[mi], bh[1], bh[3]);
                }
            }
        }
        __syncthreads();
    }

    // ---- epilogue: exp + interleaved bf16 hi/lo store of X ----
    int prl = wm * 32 + (l >> 2);
    int qcl = wn * 64 + (l & 3) * 2;
#pragma unroll
    for (int mi = 0; mi < 2; mi++) {
#pragma unroll
        for (int nj = 0; nj < 8; nj++) {
#pragma unroll
            for (int half = 0; half < 2; half++) {
                int rloc = prl + mi * 16 + half * 8;
                int qloc = qcl + nj * 8;
                float x0 = __expf(fminf(ALPHA * acc[mi][nj][half * 2 + 0], 80.f));
                float x1 = __expf(fminf(ALPHA * acc[mi][nj][half * 2 + 1], 80.f));
                __nv_bfloat16 h0 = __float2bfloat16(x0);
                __nv_bfloat16 h1 = __float2bfloat16(x1);
                __nv_bfloat16 lo0 = __float2bfloat16(x0 - __bfloat162float(h0));
                __nv_bfloat16 lo1 = __float2bfloat16(x1 - __bfloat162float(h1));
                __nv_bfloat162 hp; hp.x = h0; hp.y = h1;
                __nv_bfloat162 lp; lp.x = lo0; lp.y = lo1;
                uint2 v;
                v.x = *(uint32_t*)&hp;
                v.y = *(uint32_t*)&lp;
                g_Xil[((size_t)(pb + rloc) * HW + qb + qloc) >> 1] = v;
            }
        }
    }
}

// ---------------- 7) GEMM2: W[p][col] = sum_q X[p][q] * V[q][col], k-split ----------------
// CTA: 256 threads = 8 warps (m-split 16 rows each), N=208 full, k-chunk 16.
__global__ void __launch_bounds__(256) k_gemm2() {
    __shared__ __nv_bfloat16 sA[2][128][24];
    __shared__ __nv_bfloat16 sB[2][NV][24];

    int t = threadIdx.x, w = t >> 5, l = t & 31;
    int pb = blockIdx.x << 7;
    int ks = blockIdx.y;          // 0..7
    int q0 = ks * 512;

    float acc[26][4];
#pragma unroll
    for (int i = 0; i < 26; i++)
#pragma unroll
        for (int j = 0; j < 4; j++) acc[i][j] = 0.f;

    uint32_t sbA = smem_u32(&sA[0][0][0]);
    uint32_t sbB = smem_u32(&sB[0][0][0]);
    const uint32_t LOA = 128 * 24 * 2;
    const uint32_t LOB = NV * 24 * 2;

    int rowA = w * 16 + (l & 15);
    uint32_t colb = (uint32_t)((l >> 4) << 4);

    for (int ch = 0; ch < 32; ch++) {
        int qof = q0 + ch * 16;
        // A: 128 rows x 16 q (8 uint2 per row, interleaved hi/lo)
#pragma unroll
        for (int i = t; i < 1024; i += 256) {
            int rr = i >> 3, s = i & 7;
            uint2 v = g_Xil[((size_t)(pb + rr) * HW + qof) / 2 + s];
            ((uint32_t*)&sA[0][rr][0])[s] = v.x;
            ((uint32_t*)&sA[1][rr][0])[s] = v.y;
        }
        // B: 208 rows x 16 q (2 int4 per row per plane)
        for (int i = t; i < 416; i += 256) {
            int rr = i >> 1, s = i & 1;
            *(int4*)&sB[0][rr][s * 8] = *(const int4*)&g_Vthi[(size_t)rr * HW + qof + s * 8];
            *(int4*)&sB[1][rr][s * 8] = *(const int4*)&g_Vtlo[(size_t)rr * HW + qof + s * 8];
        }
        __syncthreads();

        uint32_t ah[4], al[4];
        uint32_t ad = sbA + (uint32_t)(rowA * 48) + colb;
        LDSM_X4(ah[0], ah[1], ah[2], ah[3], ad);
        LDSM_X4(al[0], al[1], al[2], al[3], ad + LOA);
#pragma unroll
        for (int np = 0; np < 13; np++) {
            uint32_t bd = sbB + (uint32_t)((np * 16 + (l & 15)) * 48) + colb;
            uint32_t bh[4], bl[4];
            LDSM_X4(bh[0], bh[1], bh[2], bh[3], bd);
            LDSM_X4(bl[0], bl[1], bl[2], bl[3], bd + LOB);
            mma_bf16(acc[np * 2 + 0], ah, bh[0], bh[2]);
            mma_bf16(acc[np * 2 + 0], ah, bl[0], bl[2]);
            mma_bf16(acc[np * 2 + 0], al, bh[0], bh[2]);
            mma_bf16(acc[np * 2 + 1], ah, bh[1], bh[3]);
            mma_bf16(acc[np * 2 + 1], ah, bl[1], bl[3]);
            mma_bf16(acc[np * 2 + 1], al, bh[1], bh[3]);
        }
        __syncthreads();
    }

    // epilogue: write fp32 partials
    int rbase = w * 16 + (l >> 2);
    int cb2 = (l & 3) * 2;
    float* Wp = g_Wpart + (size_t)ks * HW * NV;
#pragma unroll
    for (int np = 0; np < 13; np++) {
#pragma unroll
        for (int n8 = 0; n8 < 2; n8++) {
            int col = np * 16 + n8 * 8 + cb2;
            float* a = acc[np * 2 + n8];
            *(float2*)&Wp[(size_t)(pb + rbase) * NV + col]     = make_float2(a[0], a[1]);
            *(float2*)&Wp[(size_t)(pb + rbase + 8) * NV + col] = make_float2(a[2], a[3]);
        }
    }
}

// ---------------- 7b) reduce W partials ----------------
__global__ void k_Wred() {
    int idx = blockIdx.x * 256 + threadIdx.x;
    if (idx >= HW * NV) return;
    float s = 0.f;
#pragma unroll
    for (int ks = 0; ks < 8; ks++)
        s += g_Wpart[(size_t)ks * HW * NV + idx];
    g_W[idx] = s;
}

// ---------------- 8) combine ----------------
__global__ void k_combine() {
    int idx = blockIdx.x * 256 + threadIdx.x;   // p*64 + c
    if (idx >= HW * CO) return;
    int p = idx >> 6, c = idx & 63;
    float comb = 0.f, msum = 0.f;
#pragma unroll
    for (int k = 0; k < 3; k++) {
        if (g_maskA[k * HW + p]) {
            msum += 1.f;
            float E = g_W[p * NV + 192 + k];
            float denom = E + (4096.0f - g_nbk[k]);
            comb += (g_W[p * NV + k * 64 + c] + g_U0[c] - g_Bk[k * CO + c]) / denom;
        }
    }
    g_aligned[idx] = comb / fmaxf(msum, 1.0f);
}

// ---------------- 9) bilinear upsample 64 -> 256 ----------------
__global__ void k_up(float* __restrict__ out) {
    int idx = blockIdx.x * 256 + threadIdx.x;
    if (idx >= CO * 65536) return;
    int c = idx >> 16, Y = (idx >> 8) & 255, X = idx & 255;
    const float sc = 63.0f / 255.0f;
    float ry = (float)Y * sc, rx = (float)X * sc;
    int y0 = (int)ry, x0 = (int)rx;
    int y1 = min(y0 + 1, 63), x1 = min(x0 + 1, 63);
    float wy = ry - (float)y0, wx = rx - (float)x0;
    const float* A = g_aligned;
    float v00 = A[((y0 << 6) + x0) * CO + c];
    float v01 = A[((y0 << 6) + x1) * CO + c];
    float v10 = A[((y1 << 6) + x0) * CO + c];
    float v11 = A[((y1 << 6) + x1) * CO + c];
    float r0 = v00 * (1.f - wy) + v10 * wy;
    float r1 = v01 * (1.f - wy) + v11 * wy;
    out[idx] = r0 * (1.f - wx) + r1 * wx;
}

// ---------------- launch ----------------
extern "C" void kernel_launch(void* const* d_in, const int* in_sizes, int n_in,
                              void* d_out, int out_size) {
    const float* ufb_in = (const float*)d_in[0];   // (1,64,256,256)
    const float* fa     = (const float*)d_in[1];   // (1,256,64,64)
    const int*   fap    = (const int*)  d_in[2];   // (1,4,256,256)
    const float* fb     = (const float*)d_in[3];   // (1,256,64,64)
    const int*   fbp    = (const int*)  d_in[4];   // (1,4,256,256)
    float* out = (float*)d_out;                    // (1,64,256,256)

    k_masks<<<16, 256>>>(fap, fbp);
    k_mean<<<512, 256>>>(fa, fb);
    k_norm<<<dim3(16, 2), 256>>>(fa, fb);
    k_ufb<<<(HW * CO) / 256, 256>>>(ufb_in);
    k_ub<<<64, 256>>>();
    k_V<<<(NV * HW) / 256, 256>>>();
    k_gemm_mma<<<dim3(32, 32), 256>>>();
    k_gemm2<<<dim3(32, 8), 256>>>();
    k_Wred<<<(HW * NV) / 256, 256>>>();
    k_combine<<<(HW * CO) / 256, 256>>>();
    k_up<<<(CO * 65536) / 256, 256>>>(out);
}

// round 5
// speedup vs baseline: 2.1639x; 1.2086x over previous
#include <cuda_runtime.h>
#include <cuda_bf16.h>
#include <math.h>
#include <stdint.h>

#define HW 4096         // 64*64 spatial positions at feature res
#define CF 256          // feature channels
#define CO 64           // value channels (unalign_fb)
#define ALPHA 100.0f
#define NV 224          // GEMM2 cols: 3*64 warped + 3 E + 29 pad (14 n16 tiles)

// ---------------- device scratch (allocation-free) ----------------
__device__ uint32_t g_Xhi[(size_t)HW * HW / 2]; // bf16x2 hi plane (q,q+1)
__device__ uint32_t g_Xlo[(size_t)HW * HW / 2]; // bf16x2 lo plane
__device__ __nv_bfloat16 g_faHi[HW * CF];
__device__ __nv_bfloat16 g_faLo[HW * CF];
__device__ __nv_bfloat16 g_fbHi[HW * CF];
__device__ __nv_bfloat16 g_fbLo[HW * CF];
__device__ __nv_bfloat16 g_Vthi[NV * HW];    // V^T [col][q]
__device__ __nv_bfloat16 g_Vtlo[NV * HW];
__device__ float g_Wpart[4 * HW * NV];       // GEMM2 k-split partials
__device__ float g_W[HW * NV];
__device__ float g_ufb[HW * CO];             // downsampled values, [q][c]
__device__ float g_meanA[CF];
__device__ float g_meanB[CF];
__device__ unsigned char g_maskA[3 * HW];
__device__ unsigned char g_codeB[HW];        // 3-bit code of mask_b per q
__device__ float g_U0[CO];                   // sum_q ufb[q][c]
__device__ float g_Bk[3 * CO];               // B_k[c] = sum_{q in mb_k} ufb[q][c]
__device__ float g_nbk[3];                   // |mb_k|
__device__ float g_aligned[HW * CO];         // [p][c]

// ---------------- helpers ----------------
__device__ __forceinline__ uint32_t smem_u32(const void* p) {
    uint32_t a;
    asm("{ .reg .u64 t; cvta.to.shared.u64 t, %1; cvt.u32.u64 %0, t; }" : "=r"(a) : "l"(p));
    return a;
}

#define LDSM_X4(r0, r1, r2, r3, addr) \
    asm volatile("ldmatrix.sync.aligned.m8n8.x4.shared.b16 {%0,%1,%2,%3}, [%4];" \
        : "=r"(r0), "=r"(r1), "=r"(r2), "=r"(r3) : "r"(addr))

__device__ __forceinline__ void mma_bf16(float* c, const uint32_t* a, uint32_t b0, uint32_t b1) {
    asm volatile(
        "mma.sync.aligned.m16n8k16.row.col.f32.bf16.bf16.f32 "
        "{%0,%1,%2,%3}, {%4,%5,%6,%7}, {%8,%9}, {%0,%1,%2,%3};"
        : "+f"(c[0]), "+f"(c[1]), "+f"(c[2]), "+f"(c[3])
        : "r"(a[0]), "r"(a[1]), "r"(a[2]), "r"(a[3]), "r"(b0), "r"(b1));
}

__device__ __forceinline__ void cp16(uint32_t saddr, const void* g) {
    asm volatile("cp.async.cg.shared.global [%0], [%1], 16;" :: "r"(saddr), "l"(g));
}
#define CP_COMMIT asm volatile("cp.async.commit_group;" ::: "memory")
#define CP_WAIT1  asm volatile("cp.async.wait_group 1;" ::: "memory")
#define CP_WAIT0  asm volatile("cp.async.wait_group 0;" ::: "memory")

// ---------------- 1) masks ----------------
__global__ void k_masks(const int* __restrict__ fap, const int* __restrict__ fbp) {
    int p = blockIdx.x * 256 + threadIdx.x;
    if (p >= HW) return;
    int y = (p >> 6) << 2, x = (p & 63) << 2;
    int off = y * 256 + x;
    unsigned code = 0;
#pragma unroll
    for (int k = 0; k < 3; k++) {
        g_maskA[k * HW + p] = (fap[(k + 1) * 65536 + off] != 0) ? 1 : 0;
        if (fbp[(k + 1) * 65536 + off] != 0) code |= (1u << k);
    }
    g_codeB[p] = (unsigned char)code;
}

// ---------------- 2) per-channel spatial means ----------------
__global__ void k_mean(const float* __restrict__ fa, const float* __restrict__ fb) {
    int cb = blockIdx.x;
    int ch = cb & 255;
    const float* src = (cb < 256) ? fa : fb;
    float s = 0.f;
    for (int i = threadIdx.x; i < HW; i += 256) s += src[ch * HW + i];
    __shared__ float red[256];
    red[threadIdx.x] = s;
    __syncthreads();
    for (int st = 128; st > 0; st >>= 1) {
        if (threadIdx.x < st) red[threadIdx.x] += red[threadIdx.x + st];
        __syncthreads();
    }
    if (threadIdx.x == 0) {
        float m = red[0] / (float)HW;
        if (cb < 256) g_meanA[ch] = m; else g_meanB[ch] = m;
    }
}

// ---------------- 3) center + normalize + bf16 hi/lo split ----------------
__global__ void k_norm(const float* __restrict__ fa, const float* __restrict__ fb) {
    int p = blockIdx.x * 256 + threadIdx.x;
    if (p >= HW) return;
    const float* src;  const float* mean;
    __nv_bfloat16 *dHi, *dLo;
    if (blockIdx.y == 0) { src = fa; mean = g_meanA; dHi = g_faHi; dLo = g_faLo; }
    else                 { src = fb; mean = g_meanB; dHi = g_fbHi; dLo = g_fbLo; }
    float nsq = 0.f;
    for (int c = 0; c < CF; c++) {
        float v = src[c * HW + p] - mean[c];
        nsq += v * v;
    }
    float inv = rsqrtf(nsq);
    for (int c = 0; c < CF; c++) {
        float v = (src[c * HW + p] - mean[c]) * inv;
        __nv_bfloat16 h = __float2bfloat16(v);
        dHi[p * CF + c] = h;
        dLo[p * CF + c] = __float2bfloat16(v - __bfloat162float(h));
    }
}

// ---------------- 4) bilinear downsample 256->64 ----------------
__global__ void k_ufb(const float* __restrict__ ub) {
    int idx = blockIdx.x * 256 + threadIdx.x;
    if (idx >= HW * CO) return;
    int c = idx & 63, q = idx >> 6;
    int i = q >> 6, j = q & 63;
    const float sc = 255.0f / 63.0f;
    float ry = (float)i * sc, rx = (float)j * sc;
    int y0 = (int)ry, x0 = (int)rx;
    int y1 = min(y0 + 1, 255), x1 = min(x0 + 1, 255);
    float wy = ry - (float)y0, wx = rx - (float)x0;
    const float* b = ub + c * 65536;
    float v00 = b[y0 * 256 + x0], v01 = b[y0 * 256 + x1];
    float v10 = b[y1 * 256 + x0], v11 = b[y1 * 256 + x1];
    float r0 = v00 * (1.f - wy) + v10 * wy;
    float r1 = v01 * (1.f - wy) + v11 * wy;
    g_ufb[q * CO + c] = r0 * (1.f - wx) + r1 * wx;
}

// ---------------- 5) U0[c], Bk[k][c], nbk ----------------
__global__ void k_ub() {
    int c = blockIdx.x;
    __shared__ float s_acc[4];
    __shared__ int   s_n[3];
    if (threadIdx.x < 4) s_acc[threadIdx.x] = 0.f;
    if (threadIdx.x < 3) s_n[threadIdx.x] = 0;
    __syncthreads();
    float a0 = 0, b0 = 0, b1 = 0, b2 = 0;
    int n0 = 0, n1 = 0, n2 = 0;
    for (int q = threadIdx.x; q < HW; q += 256) {
        float u = g_ufb[q * CO + c];
        int code = g_codeB[q];
        a0 += u;
        if (code & 1) { b0 += u; n0++; }
        if (code & 2) { b1 += u; n1++; }
        if (code & 4) { b2 += u; n2++; }
    }
    atomicAdd(&s_acc[0], a0);
    atomicAdd(&s_acc[1], b0);
    atomicAdd(&s_acc[2], b1);
    atomicAdd(&s_acc[3], b2);
    if (c == 0) {
        atomicAdd(&s_n[0], n0); atomicAdd(&s_n[1], n1); atomicAdd(&s_n[2], n2);
    }
    __syncthreads();
    if (threadIdx.x == 0) g_U0[c] = s_acc[0];
    if (threadIdx.x < 3) {
        g_Bk[threadIdx.x * CO + c] = s_acc[1 + threadIdx.x];
        if (c == 0) g_nbk[threadIdx.x] = (float)s_n[threadIdx.x];
    }
}

// ---------------- 5b) build V^T planes ----------------
__global__ void k_V() {
    int idx = blockIdx.x * 256 + threadIdx.x;   // col*HW + q
    if (idx >= NV * HW) return;
    int col = idx >> 12, q = idx & 4095;
    float v = 0.f;
    int code = g_codeB[q];
    if (col < 192) {
        int k = col >> 6, c = col & 63;
        v = ((code >> k) & 1) ? g_ufb[q * CO + c] : 0.f;
    } else if (col < 195) {
        v = (float)((code >> (col - 192)) & 1);
    }
    __nv_bfloat16 h = __float2bfloat16(v);
    g_Vthi[idx] = h;
    g_Vtlo[idx] = __float2bfloat16(v - __bfloat162float(h));
}

// ---------------- 6) GEMM1: split-bf16 S-GEMM, cp.async double-buffered ----------------
#define G1_PLANE 10240              // 128 rows * 80 bytes
#define G1_SMEM  (2 * 4 * G1_PLANE) // 81920

__device__ __forceinline__ void g1_prefetch(uint32_t sb, int buf, int kc,
                                            int pb, int qb, int t) {
    int kof = kc * 32;
#pragma unroll
    for (int i = 0; i < 8; i++) {
        int v = t + i * 256;
        int plane = v >> 9, r = (v >> 2) & 127, seg = v & 3;
        uint32_t sa = sb + (uint32_t)(buf * (4 * G1_PLANE) + plane * G1_PLANE + r * 80 + seg * 16);
        const __nv_bfloat16* src = (plane == 0) ? g_faHi : (plane == 1) ? g_faLo
                                 : (plane == 2) ? g_fbHi : g_fbLo;
        int rowb = (plane < 2) ? pb : qb;
        const void* ga = (const char*)src + ((size_t)(rowb + r) * CF + kof + seg * 8) * 2;
        cp16(sa, ga);
    }
}

__global__ void __launch_bounds__(256, 2) k_gemm_mma() {
    extern __shared__ char smem[];
    uint32_t sb = smem_u32(smem);
    int t = threadIdx.x, w = t >> 5, l = t & 31;
    int qb = blockIdx.x << 7, pb = blockIdx.y << 7;
    int wm = w >> 1, wn = w & 1;

    float acc[2][8][4] = {};

    int rowA = wm * 32 + (l & 15);
    int rowB = wn * 64 + (l & 15);
    uint32_t colb = (uint32_t)((l >> 4) << 4);

    g1_prefetch(sb, 0, 0, pb, qb, t); CP_COMMIT;

    for (int kc = 0; kc < 8; kc++) {
        if (kc < 7) { g1_prefetch(sb, (kc + 1) & 1, kc + 1, pb, qb, t); CP_COMMIT; CP_WAIT1; }
        else CP_WAIT0;
        __syncthreads();

        uint32_t baseA = sb + (uint32_t)((kc & 1) * (4 * G1_PLANE));
        uint32_t baseB = baseA + 2 * G1_PLANE;

#pragma unroll
        for (int kk2 = 0; kk2 < 2; kk2++) {
            uint32_t kb = (uint32_t)(kk2 * 32) + colb;
            uint32_t ah[2][4], al[2][4];
#pragma unroll
            for (int mi = 0; mi < 2; mi++) {
                uint32_t ad = baseA + (uint32_t)((rowA + mi * 16) * 80) + kb;
                LDSM_X4(ah[mi][0], ah[mi][1], ah[mi][2], ah[mi][3], ad);
                LDSM_X4(al[mi][0], al[mi][1], al[mi][2], al[mi][3], ad + G1_PLANE);
            }
#pragma unroll
            for (int np = 0; np < 4; np++) {
                uint32_t bd = baseB + (uint32_t)((rowB + np * 16) * 80) + kb;
                uint32_t bh[4], bl[4];
                LDSM_X4(bh[0], bh[1], bh[2], bh[3], bd);
                LDSM_X4(bl[0], bl[1], bl[2], bl[3], bd + G1_PLANE);
#pragma unroll
                for (int mi = 0; mi < 2; mi++) {
                    mma_bf16(acc[mi][np * 2 + 0], ah[mi], bh[0], bh[2]);
                    mma_bf16(acc[mi][np * 2 + 0], ah[mi], bl[0], bl[2]);
                    mma_bf16(acc[mi][np * 2 + 0], al[mi], bh[0], bh[2]);
                    mma_bf16(acc[mi][np * 2 + 1], ah[mi], bh[1], bh[3]);
                    mma_bf16(acc[mi][np * 2 + 1], ah[mi], bl[1], bl[3]);
                    mma_bf16(acc[mi][np * 2 + 1], al[mi], bh[1], bh[3]);
                }
            }
        }
        __syncthreads();
    }

    // ---- epilogue: exp + bf16 hi/lo plane stores ----
    int prl = wm * 32 + (l >> 2);
    int qcl = wn * 64 + (l & 3) * 2;
#pragma unroll
    for (int mi = 0; mi < 2; mi++) {
#pragma unroll
        for (int nj = 0; nj < 8; nj++) {
#pragma unroll
            for (int half = 0; half < 2; half++) {
                int rloc = prl + mi * 16 + half * 8;
                int qloc = qcl + nj * 8;
                float x0 = __expf(fminf(ALPHA * acc[mi][nj][half * 2 + 0], 80.f));
                float x1 = __expf(fminf(ALPHA * acc[mi][nj][half * 2 + 1], 80.f));
                __nv_bfloat16 h0 = __float2bfloat16(x0);
                __nv_bfloat16 h1 = __float2bfloat16(x1);
                __nv_bfloat16 lo0 = __float2bfloat16(x0 - __bfloat162float(h0));
                __nv_bfloat16 lo1 = __float2bfloat16(x1 - __bfloat162float(h1));
                __nv_bfloat162 hp; hp.x = h0; hp.y = h1;
                __nv_bfloat162 lp; lp.x = lo0; lp.y = lo1;
                size_t idx = ((size_t)(pb + rloc) * HW + qb + qloc) >> 1;
                g_Xhi[idx] = *(uint32_t*)&hp;
                g_Xlo[idx] = *(uint32_t*)&lp;
            }
        }
    }
}

// ---------------- 7) GEMM2: W = X @ V^T, cp.async double-buffered ----------------
// grid (64, 4): M-tile 64, k-range 1024, chunk 32 q. 8 warps: wm 0..3 (m16), wn 0..1 (112 cols)
#define G2_APLANE (64 * 80)                      // 5120
#define G2_BPLANE (NV * 80)                      // 17920
#define G2_BUF    (2 * G2_APLANE + 2 * G2_BPLANE)// 46080
#define G2_SMEM   (2 * G2_BUF)                   // 92160

__device__ __forceinline__ void g2_prefetch(uint32_t sb, int buf, int qof, int pb, int t) {
#pragma unroll
    for (int i = 0; i < 9; i++) {
        int v = t + i * 256;
        if (v < 512) {
            int plane = v >> 8, r = (v >> 2) & 63, seg = v & 3;
            uint32_t sa = sb + (uint32_t)(buf * G2_BUF + plane * G2_APLANE + r * 80 + seg * 16);
            const uint32_t* xp = plane ? g_Xlo : g_Xhi;
            const void* ga = (const char*)xp + ((size_t)(pb + r) * HW + qof) * 2 + seg * 16;
            cp16(sa, ga);
        } else {
            int v2 = v - 512;
            int plane = (v2 >= 896) ? 1 : 0;
            int r = (v2 - plane * 896) >> 2, seg = v2 & 3;
            uint32_t sa = sb + (uint32_t)(buf * G2_BUF + 2 * G2_APLANE + plane * G2_BPLANE + r * 80 + seg * 16);
            const __nv_bfloat16* vp = plane ? g_Vtlo : g_Vthi;
            const void* ga = (const char*)vp + ((size_t)r * HW + qof + seg * 8) * 2;
            cp16(sa, ga);
        }
    }
}

__global__ void __launch_bounds__(256, 2) k_gemm2() {
    extern __shared__ char smem[];
    uint32_t sb = smem_u32(smem);
    int t = threadIdx.x, w = t >> 5, l = t & 31;
    int pb = blockIdx.x << 6;
    int q0 = blockIdx.y << 10;
    int wm = w >> 1, wn = w & 1;

    float acc[14][4] = {};

    uint32_t arow = (uint32_t)((wm * 16 + (l & 15)) * 80);
    uint32_t lofs = (uint32_t)((l >> 4) << 4);

    g2_prefetch(sb, 0, q0, pb, t); CP_COMMIT;

    for (int ch = 0; ch < 32; ch++) {
        if (ch < 31) { g2_prefetch(sb, (ch + 1) & 1, q0 + (ch + 1) * 32, pb, t); CP_COMMIT; CP_WAIT1; }
        else CP_WAIT0;
        __syncthreads();

        uint32_t baseA = sb + (uint32_t)((ch & 1) * G2_BUF);
        uint32_t baseB = baseA + 2 * G2_APLANE;

#pragma unroll
        for (int kk2 = 0; kk2 < 2; kk2++) {
            uint32_t kb = (uint32_t)(kk2 * 32) + lofs;
            uint32_t ah[4], al[4];
            uint32_t ad = baseA + arow + kb;
            LDSM_X4(ah[0], ah[1], ah[2], ah[3], ad);
            LDSM_X4(al[0], al[1], al[2], al[3], ad + G2_APLANE);
#pragma unroll
            for (int np = 0; np < 7; np++) {
                uint32_t bd = baseB + (uint32_t)((wn * 112 + np * 16 + (l & 15)) * 80) + kb;
                uint32_t bh[4], bl[4];
                LDSM_X4(bh[0], bh[1], bh[2], bh[3], bd);
                LDSM_X4(bl[0], bl[1], bl[2], bl[3], bd + G2_BPLANE);
                mma_bf16(acc[np * 2 + 0], ah, bh[0], bh[2]);
                mma_bf16(acc[np * 2 + 0], ah, bl[0], bl[2]);
                mma_bf16(acc[np * 2 + 0], al, bh[0], bh[2]);
                mma_bf16(acc[np * 2 + 1], ah, bh[1], bh[3]);
                mma_bf16(acc[np * 2 + 1], ah, bl[1], bl[3]);
                mma_bf16(acc[np * 2 + 1], al, bh[1], bh[3]);
            }
        }
        __syncthreads();
    }

    // epilogue: fp32 partials
    int r0 = pb + wm * 16 + (l >> 2);
    int cb2 = (l & 3) * 2;
    float* Wp = g_Wpart + (size_t)blockIdx.y * HW * NV;
#pragma unroll
    for (int np = 0; np < 7; np++) {
#pragma unroll
        for (int n8 = 0; n8 < 2; n8++) {
            int col = wn * 112 + np * 16 + n8 * 8 + cb2;
            float* a = acc[np * 2 + n8];
            *(float2*)&Wp[(size_t)r0 * NV + col]       = make_float2(a[0], a[1]);
            *(float2*)&Wp[(size_t)(r0 + 8) * NV + col] = make_float2(a[2], a[3]);
        }
    }
}

// ---------------- 7b) reduce W partials ----------------
__global__ void k_Wred() {
    int idx = blockIdx.x * 256 + threadIdx.x;
    if (idx >= HW * NV) return;
    float s = 0.f;
#pragma unroll
    for (int ks = 0; ks < 4; ks++)
        s += g_Wpart[(size_t)ks * HW * NV + idx];
    g_W[idx] = s;
}

// ---------------- 8) combine ----------------
__global__ void k_combine() {
    int idx = blockIdx.x * 256 + threadIdx.x;   // p*64 + c
    if (idx >= HW * CO) return;
    int p = idx >> 6, c = idx & 63;
    float comb = 0.f, msum = 0.f;
#pragma unroll
    for (int k = 0; k < 3; k++) {
        if (g_maskA[k * HW + p]) {
            msum += 1.f;
            float E = g_W[p * NV + 192 + k];
            float denom = E + (4096.0f - g_nbk[k]);
            comb += (g_W[p * NV + k * 64 + c] + g_U0[c] - g_Bk[k * CO + c]) / denom;
        }
    }
    g_aligned[idx] = comb / fmaxf(msum, 1.0f);
}

// ---------------- 9) bilinear upsample 64 -> 256 ----------------
__global__ void k_up(float* __restrict__ out) {
    int idx = blockIdx.x * 256 + threadIdx.x;
    if (idx >= CO * 65536) return;
    int c = idx >> 16, Y = (idx >> 8) & 255, X = idx & 255;
    const float sc = 63.0f / 255.0f;
    float ry = (float)Y * sc, rx = (float)X * sc;
    int y0 = (int)ry, x0 = (int)rx;
    int y1 = min(y0 + 1, 63), x1 = min(x0 + 1, 63);
    float wy = ry - (float)y0, wx = rx - (float)x0;
    const float* A = g_aligned;
    float v00 = A[((y0 << 6) + x0) * CO + c];
    float v01 = A[((y0 << 6) + x1) * CO + c];
    float v10 = A[((y1 << 6) + x0) * CO + c];
    float v11 = A[((y1 << 6) + x1) * CO + c];
    float r0 = v00 * (1.f - wy) + v10 * wy;
    float r1 = v01 * (1.f - wy) + v11 * wy;
    out[idx] = r0 * (1.f - wx) + r1 * wx;
}

// ---------------- launch ----------------
extern "C" void kernel_launch(void* const* d_in, const int* in_sizes, int n_in,
                              void* d_out, int out_size) {
    const float* ufb_in = (const float*)d_in[0];   // (1,64,256,256)
    const float* fa     = (const float*)d_in[1];   // (1,256,64,64)
    const int*   fap    = (const int*)  d_in[2];   // (1,4,256,256)
    const float* fb     = (const float*)d_in[3];   // (1,256,64,64)
    const int*   fbp    = (const int*)  d_in[4];   // (1,4,256,256)
    float* out = (float*)d_out;                    // (1,64,256,256)

    cudaFuncSetAttribute(k_gemm_mma, cudaFuncAttributeMaxDynamicSharedMemorySize, G1_SMEM);
    cudaFuncSetAttribute(k_gemm2,    cudaFuncAttributeMaxDynamicSharedMemorySize, G2_SMEM);

    k_masks<<<16, 256>>>(fap, fbp);
    k_mean<<<512, 256>>>(fa, fb);
    k_norm<<<dim3(16, 2), 256>>>(fa, fb);
    k_gemm_mma<<<dim3(32, 32), 256, G1_SMEM>>>();          // 4th launch -> profiled
    k_ufb<<<(HW * CO) / 256, 256>>>(ufb_in);
    k_ub<<<64, 256>>>();
    k_V<<<(NV * HW) / 256, 256>>>();
    k_gemm2<<<dim3(64, 4), 256, G2_SMEM>>>();
    k_Wred<<<(HW * NV) / 256, 256>>>();
    k_combine<<<(HW * CO) / 256, 256>>>();
    k_up<<<(CO * 65536) / 256, 256>>>(out);
}

// round 6
// speedup vs baseline: 2.1730x; 1.0042x over previous
#include <cuda_runtime.h>
#include <cuda_bf16.h>
#include <math.h>
#include <stdint.h>

#define HW 4096         // 64*64 spatial positions at feature res
#define CF 256          // feature channels
#define CO 64           // value channels (unalign_fb)
#define ALPHA 100.0f
#define NV 224          // GEMM2 cols: 3*64 warped + 3 E + 29 pad (14 n16 tiles)

// ---------------- device scratch (allocation-free) ----------------
__device__ uint32_t g_Xhi[(size_t)HW * HW / 2]; // bf16x2 hi plane (q,q+1)
__device__ uint32_t g_Xlo[(size_t)HW * HW / 2]; // bf16x2 lo plane
__device__ __nv_bfloat16 g_faHi[HW * CF];
__device__ __nv_bfloat16 g_faLo[HW * CF];
__device__ __nv_bfloat16 g_fbHi[HW * CF];
__device__ __nv_bfloat16 g_fbLo[HW * CF];
__device__ __nv_bfloat16 g_Vthi[NV * HW];    // V^T [col][q]
__device__ __nv_bfloat16 g_Vtlo[NV * HW];
__device__ float g_Wpart[4 * HW * NV];       // GEMM2 k-split partials
__device__ float g_W[HW * NV];
__device__ float g_ufb[HW * CO];             // downsampled values, [q][c]
__device__ float g_meanA[CF];
__device__ float g_meanB[CF];
__device__ unsigned char g_maskA[3 * HW];
__device__ unsigned char g_codeB[HW];        // 3-bit code of mask_b per q
__device__ float g_U0[CO];                   // sum_q ufb[q][c]
__device__ float g_Bk[3 * CO];               // B_k[c] = sum_{q in mb_k} ufb[q][c]
__device__ float g_nbk[3];                   // |mb_k|
__device__ float g_aligned[HW * CO];         // [p][c]

// ---------------- helpers ----------------
__device__ __forceinline__ uint32_t smem_u32(const void* p) {
    uint32_t a;
    asm("{ .reg .u64 t; cvta.to.shared.u64 t, %1; cvt.u32.u64 %0, t; }" : "=r"(a) : "l"(p));
    return a;
}

#define LDSM_X4(r0, r1, r2, r3, addr) \
    asm volatile("ldmatrix.sync.aligned.m8n8.x4.shared.b16 {%0,%1,%2,%3}, [%4];" \
        : "=r"(r0), "=r"(r1), "=r"(r2), "=r"(r3) : "r"(addr))

__device__ __forceinline__ void mma_bf16(float* c, const uint32_t* a, uint32_t b0, uint32_t b1) {
    asm volatile(
        "mma.sync.aligned.m16n8k16.row.col.f32.bf16.bf16.f32 "
        "{%0,%1,%2,%3}, {%4,%5,%6,%7}, {%8,%9}, {%0,%1,%2,%3};"
        : "+f"(c[0]), "+f"(c[1]), "+f"(c[2]), "+f"(c[3])
        : "r"(a[0]), "r"(a[1]), "r"(a[2]), "r"(a[3]), "r"(b0), "r"(b1));
}

__device__ __forceinline__ void cp16(uint32_t saddr, const void* g) {
    asm volatile("cp.async.cg.shared.global [%0], [%1], 16;" :: "r"(saddr), "l"(g));
}
#define CP_COMMIT asm volatile("cp.async.commit_group;" ::: "memory")
#define CP_WAIT1  asm volatile("cp.async.wait_group 1;" ::: "memory")
#define CP_WAIT0  asm volatile("cp.async.wait_group 0;" ::: "memory")

// ---------------- 1) masks ----------------
__global__ void k_masks(const int* __restrict__ fap, const int* __restrict__ fbp) {
    int p = blockIdx.x * 256 + threadIdx.x;
    if (p >= HW) return;
    int y = (p >> 6) << 2, x = (p & 63) << 2;
    int off = y * 256 + x;
    unsigned code = 0;
#pragma unroll
    for (int k = 0; k < 3; k++) {
        g_maskA[k * HW + p] = (fap[(k + 1) * 65536 + off] != 0) ? 1 : 0;
        if (fbp[(k + 1) * 65536 + off] != 0) code |= (1u << k);
    }
    g_codeB[p] = (unsigned char)code;
}

// ---------------- 2) per-channel spatial means ----------------
__global__ void k_mean(const float* __restrict__ fa, const float* __restrict__ fb) {
    int cb = blockIdx.x;
    int ch = cb & 255;
    const float* src = (cb < 256) ? fa : fb;
    float s = 0.f;
    for (int i = threadIdx.x; i < HW; i += 256) s += src[ch * HW + i];
    __shared__ float red[256];
    red[threadIdx.x] = s;
    __syncthreads();
    for (int st = 128; st > 0; st >>= 1) {
        if (threadIdx.x < st) red[threadIdx.x] += red[threadIdx.x + st];
        __syncthreads();
    }
    if (threadIdx.x == 0) {
        float m = red[0] / (float)HW;
        if (cb < 256) g_meanA[ch] = m; else g_meanB[ch] = m;
    }
}

// ---------------- 3) center + normalize + bf16 hi/lo split ----------------
__global__ void k_norm(const float* __restrict__ fa, const float* __restrict__ fb) {
    int p = blockIdx.x * 256 + threadIdx.x;
    if (p >= HW) return;
    const float* src;  const float* mean;
    __nv_bfloat16 *dHi, *dLo;
    if (blockIdx.y == 0) { src = fa; mean = g_meanA; dHi = g_faHi; dLo = g_faLo; }
    else                 { src = fb; mean = g_meanB; dHi = g_fbHi; dLo = g_fbLo; }
    float nsq = 0.f;
    for (int c = 0; c < CF; c++) {
        float v = src[c * HW + p] - mean[c];
        nsq += v * v;
    }
    float inv = rsqrtf(nsq);
    for (int c = 0; c < CF; c++) {
        float v = (src[c * HW + p] - mean[c]) * inv;
        __nv_bfloat16 h = __float2bfloat16(v);
        dHi[p * CF + c] = h;
        dLo[p * CF + c] = __float2bfloat16(v - __bfloat162float(h));
    }
}

// ---------------- 4) bilinear downsample 256->64 ----------------
__global__ void k_ufb(const float* __restrict__ ub) {
    int idx = blockIdx.x * 256 + threadIdx.x;
    if (idx >= HW * CO) return;
    int c = idx & 63, q = idx >> 6;
    int i = q >> 6, j = q & 63;
    const float sc = 255.0f / 63.0f;
    float ry = (float)i * sc, rx = (float)j * sc;
    int y0 = (int)ry, x0 = (int)rx;
    int y1 = min(y0 + 1, 255), x1 = min(x0 + 1, 255);
    float wy = ry - (float)y0, wx = rx - (float)x0;
    const float* b = ub + c * 65536;
    float v00 = b[y0 * 256 + x0], v01 = b[y0 * 256 + x1];
    float v10 = b[y1 * 256 + x0], v11 = b[y1 * 256 + x1];
    float r0 = v00 * (1.f - wy) + v10 * wy;
    float r1 = v01 * (1.f - wy) + v11 * wy;
    g_ufb[q * CO + c] = r0 * (1.f - wx) + r1 * wx;
}

// ---------------- 5) U0[c], Bk[k][c], nbk ----------------
__global__ void k_ub() {
    int c = blockIdx.x;
    __shared__ float s_acc[4];
    __shared__ int   s_n[3];
    if (threadIdx.x < 4) s_acc[threadIdx.x] = 0.f;
    if (threadIdx.x < 3) s_n[threadIdx.x] = 0;
    __syncthreads();
    float a0 = 0, b0 = 0, b1 = 0, b2 = 0;
    int n0 = 0, n1 = 0, n2 = 0;
    for (int q = threadIdx.x; q < HW; q += 256) {
        float u = g_ufb[q * CO + c];
        int code = g_codeB[q];
        a0 += u;
        if (code & 1) { b0 += u; n0++; }
        if (code & 2) { b1 += u; n1++; }
        if (code & 4) { b2 += u; n2++; }
    }
    atomicAdd(&s_acc[0], a0);
    atomicAdd(&s_acc[1], b0);
    atomicAdd(&s_acc[2], b1);
    atomicAdd(&s_acc[3], b2);
    if (c == 0) {
        atomicAdd(&s_n[0], n0); atomicAdd(&s_n[1], n1); atomicAdd(&s_n[2], n2);
    }
    __syncthreads();
    if (threadIdx.x == 0) g_U0[c] = s_acc[0];
    if (threadIdx.x < 3) {
        g_Bk[threadIdx.x * CO + c] = s_acc[1 + threadIdx.x];
        if (c == 0) g_nbk[threadIdx.x] = (float)s_n[threadIdx.x];
    }
}

// ---------------- 5b) build V^T planes ----------------
__global__ void k_V() {
    int idx = blockIdx.x * 256 + threadIdx.x;   // col*HW + q
    if (idx >= NV * HW) return;
    int col = idx >> 12, q = idx & 4095;
    float v = 0.f;
    int code = g_codeB[q];
    if (col < 192) {
        int k = col >> 6, c = col & 63;
        v = ((code >> k) & 1) ? g_ufb[q * CO + c] : 0.f;
    } else if (col < 195) {
        v = (float)((code >> (col - 192)) & 1);
    }
    __nv_bfloat16 h = __float2bfloat16(v);
    g_Vthi[idx] = h;
    g_Vtlo[idx] = __float2bfloat16(v - __bfloat162float(h));
}

// ---------------- 6) GEMM1: split-bf16 S-GEMM, cp.async double-buffered ----------------
#define G1_PLANE 10240              // 128 rows * 80 bytes
#define G1_SMEM  (2 * 4 * G1_PLANE) // 81920

__device__ __forceinline__ void g1_prefetch(uint32_t sb, int buf, int kc,
                                            int pb, int qb, int t) {
    int kof = kc * 32;
#pragma unroll
    for (int i = 0; i < 8; i++) {
        int v = t + i * 256;
        int plane = v >> 9, r = (v >> 2) & 127, seg = v & 3;
        uint32_t sa = sb + (uint32_t)(buf * (4 * G1_PLANE) + plane * G1_PLANE + r * 80 + seg * 16);
        const __nv_bfloat16* src = (plane == 0) ? g_faHi : (plane == 1) ? g_faLo
                                 : (plane == 2) ? g_fbHi : g_fbLo;
        int rowb = (plane < 2) ? pb : qb;
        const void* ga = (const char*)src + ((size_t)(rowb + r) * CF + kof + seg * 8) * 2;
        cp16(sa, ga);
    }
}

__global__ void __launch_bounds__(256, 2) k_gemm_mma() {
    extern __shared__ char smem[];
    uint32_t sb = smem_u32(smem);
    int t = threadIdx.x, w = t >> 5, l = t & 31;
    int qb = blockIdx.x << 7, pb = blockIdx.y << 7;
    int wm = w >> 1, wn = w & 1;

    float acc[2][8][4] = {};

    int rowA = wm * 32 + (l & 15);
    int rowB = wn * 64 + (l & 15);
    uint32_t colb = (uint32_t)((l >> 4) << 4);

    g1_prefetch(sb, 0, 0, pb, qb, t); CP_COMMIT;

    for (int kc = 0; kc < 8; kc++) {
        if (kc < 7) { g1_prefetch(sb, (kc + 1) & 1, kc + 1, pb, qb, t); CP_COMMIT; CP_WAIT1; }
        else CP_WAIT0;
        __syncthreads();

        uint32_t baseA = sb + (uint32_t)((kc & 1) * (4 * G1_PLANE));
        uint32_t baseB = baseA + 2 * G1_PLANE;

#pragma unroll
        for (int kk2 = 0; kk2 < 2; kk2++) {
            uint32_t kb = (uint32_t)(kk2 * 32) + colb;
            uint32_t ah[2][4], al[2][4];
#pragma unroll
            for (int mi = 0; mi < 2; mi++) {
                uint32_t ad = baseA + (uint32_t)((rowA + mi * 16) * 80) + kb;
                LDSM_X4(ah[mi][0], ah[mi][1], ah[mi][2], ah[mi][3], ad);
                LDSM_X4(al[mi][0], al[mi][1], al[mi][2], al[mi][3], ad + G1_PLANE);
            }
#pragma unroll
            for (int np = 0; np < 4; np++) {
                uint32_t bd = baseB + (uint32_t)((rowB + np * 16) * 80) + kb;
                uint32_t bh[4], bl[4];
                LDSM_X4(bh[0], bh[1], bh[2], bh[3], bd);
                LDSM_X4(bl[0], bl[1], bl[2], bl[3], bd + G1_PLANE);
                // combo-major ordering: consecutive MMAs hit different accumulators
                mma_bf16(acc[0][np * 2 + 0], ah[0], bh[0], bh[2]);
                mma_bf16(acc[0][np * 2 + 1], ah[0], bh[1], bh[3]);
                mma_bf16(acc[1][np * 2 + 0], ah[1], bh[0], bh[2]);
                mma_bf16(acc[1][np * 2 + 1], ah[1], bh[1], bh[3]);
                mma_bf16(acc[0][np * 2 + 0], ah[0], bl[0], bl[2]);
                mma_bf16(acc[0][np * 2 + 1], ah[0], bl[1], bl[3]);
                mma_bf16(acc[1][np * 2 + 0], ah[1], bl[0], bl[2]);
                mma_bf16(acc[1][np * 2 + 1], ah[1], bl[1], bl[3]);
                mma_bf16(acc[0][np * 2 + 0], al[0], bh[0], bh[2]);
                mma_bf16(acc[0][np * 2 + 1], al[0], bh[1], bh[3]);
                mma_bf16(acc[1][np * 2 + 0], al[1], bh[0], bh[2]);
                mma_bf16(acc[1][np * 2 + 1], al[1], bh[1], bh[3]);
            }
        }
        __syncthreads();
    }

    // ---- epilogue: exp + bf16 hi/lo plane stores ----
    int prl = wm * 32 + (l >> 2);
    int qcl = wn * 64 + (l & 3) * 2;
#pragma unroll
    for (int mi = 0; mi < 2; mi++) {
#pragma unroll
        for (int nj = 0; nj < 8; nj++) {
#pragma unroll
            for (int half = 0; half < 2; half++) {
                int rloc = prl + mi * 16 + half * 8;
                int qloc = qcl + nj * 8;
                float x0 = __expf(fminf(ALPHA * acc[mi][nj][half * 2 + 0], 80.f));
                float x1 = __expf(fminf(ALPHA * acc[mi][nj][half * 2 + 1], 80.f));
                __nv_bfloat16 h0 = __float2bfloat16(x0);
                __nv_bfloat16 h1 = __float2bfloat16(x1);
                __nv_bfloat16 lo0 = __float2bfloat16(x0 - __bfloat162float(h0));
                __nv_bfloat16 lo1 = __float2bfloat16(x1 - __bfloat162float(h1));
                __nv_bfloat162 hp; hp.x = h0; hp.y = h1;
                __nv_bfloat162 lp; lp.x = lo0; lp.y = lo1;
                size_t idx = ((size_t)(pb + rloc) * HW + qb + qloc) >> 1;
                g_Xhi[idx] = *(uint32_t*)&hp;
                g_Xlo[idx] = *(uint32_t*)&lp;
            }
        }
    }
}

// ---------------- 7) GEMM2: W = X @ V^T, cp.async double-buffered ----------------
#define G2_APLANE (64 * 80)                      // 5120
#define G2_BPLANE (NV * 80)                      // 17920
#define G2_BUF    (2 * G2_APLANE + 2 * G2_BPLANE)// 46080
#define G2_SMEM   (2 * G2_BUF)                   // 92160

__device__ __forceinline__ void g2_prefetch(uint32_t sb, int buf, int qof, int pb, int t) {
#pragma unroll
    for (int i = 0; i < 9; i++) {
        int v = t + i * 256;
        if (v < 512) {
            int plane = v >> 8, r = (v >> 2) & 63, seg = v & 3;
            uint32_t sa = sb + (uint32_t)(buf * G2_BUF + plane * G2_APLANE + r * 80 + seg * 16);
            const uint32_t* xp = plane ? g_Xlo : g_Xhi;
            const void* ga = (const char*)xp + ((size_t)(pb + r) * HW + qof) * 2 + seg * 16;
            cp16(sa, ga);
        } else {
            int v2 = v - 512;
            int plane = (v2 >= 896) ? 1 : 0;
            int r = (v2 - plane * 896) >> 2, seg = v2 & 3;
            uint32_t sa = sb + (uint32_t)(buf * G2_BUF + 2 * G2_APLANE + plane * G2_BPLANE + r * 80 + seg * 16);
            const __nv_bfloat16* vp = plane ? g_Vtlo : g_Vthi;
            const void* ga = (const char*)vp + ((size_t)r * HW + qof + seg * 8) * 2;
            cp16(sa, ga);
        }
    }
}

__global__ void __launch_bounds__(256, 2) k_gemm2() {
    extern __shared__ char smem[];
    uint32_t sb = smem_u32(smem);
    int t = threadIdx.x, w = t >> 5, l = t & 31;
    int pb = blockIdx.x << 6;
    int q0 = blockIdx.y << 10;
    int wm = w >> 1, wn = w & 1;

    float acc[14][4] = {};

    uint32_t arow = (uint32_t)((wm * 16 + (l & 15)) * 80);
    uint32_t lofs = (uint32_t)((l >> 4) << 4);

    g2_prefetch(sb, 0, q0, pb, t); CP_COMMIT;

    for (int ch = 0; ch < 32; ch++) {
        if (ch < 31) { g2_prefetch(sb, (ch + 1) & 1, q0 + (ch + 1) * 32, pb, t); CP_COMMIT; CP_WAIT1; }
        else CP_WAIT0;
        __syncthreads();

        uint32_t baseA = sb + (uint32_t)((ch & 1) * G2_BUF);
        uint32_t baseB = baseA + 2 * G2_APLANE;

#pragma unroll
        for (int kk2 = 0; kk2 < 2; kk2++) {
            uint32_t kb = (uint32_t)(kk2 * 32) + lofs;
            uint32_t ah[4], al[4];
            uint32_t ad = baseA + arow + kb;
            LDSM_X4(ah[0], ah[1], ah[2], ah[3], ad);
            LDSM_X4(al[0], al[1], al[2], al[3], ad + G2_APLANE);
            // np pairs: 8 independent MMAs between same-acc rewrites
#pragma unroll
            for (int npp = 0; npp < 3; npp++) {
                int np = npp * 2;
                uint32_t bd0 = baseB + (uint32_t)((wn * 112 + np * 16 + (l & 15)) * 80) + kb;
                uint32_t bd1 = bd0 + 16 * 80;
                uint32_t bh0[4], bl0[4], bh1[4], bl1[4];
                LDSM_X4(bh0[0], bh0[1], bh0[2], bh0[3], bd0);
                LDSM_X4(bl0[0], bl0[1], bl0[2], bl0[3], bd0 + G2_BPLANE);
                LDSM_X4(bh1[0], bh1[1], bh1[2], bh1[3], bd1);
                LDSM_X4(bl1[0], bl1[1], bl1[2], bl1[3], bd1 + G2_BPLANE);
                mma_bf16(acc[np * 2 + 0], ah, bh0[0], bh0[2]);
                mma_bf16(acc[np * 2 + 1], ah, bh0[1], bh0[3]);
                mma_bf16(acc[np * 2 + 2], ah, bh1[0], bh1[2]);
                mma_bf16(acc[np * 2 + 3], ah, bh1[1], bh1[3]);
                mma_bf16(acc[np * 2 + 0], ah, bl0[0], bl0[2]);
                mma_bf16(acc[np * 2 + 1], ah, bl0[1], bl0[3]);
                mma_bf16(acc[np * 2 + 2], ah, bl1[0], bl1[2]);
                mma_bf16(acc[np * 2 + 3], ah, bl1[1], bl1[3]);
                mma_bf16(acc[np * 2 + 0], al, bh0[0], bh0[2]);
                mma_bf16(acc[np * 2 + 1], al, bh0[1], bh0[3]);
                mma_bf16(acc[np * 2 + 2], al, bh1[0], bh1[2]);
                mma_bf16(acc[np * 2 + 3], al, bh1[1], bh1[3]);
            }
            {   // tail np=6
                uint32_t bd = baseB + (uint32_t)((wn * 112 + 6 * 16 + (l & 15)) * 80) + kb;
                uint32_t bh[4], bl[4];
                LDSM_X4(bh[0], bh[1], bh[2], bh[3], bd);
                LDSM_X4(bl[0], bl[1], bl[2], bl[3], bd + G2_BPLANE);
                mma_bf16(acc[12], ah, bh[0], bh[2]);
                mma_bf16(acc[13], ah, bh[1], bh[3]);
                mma_bf16(acc[12], ah, bl[0], bl[2]);
                mma_bf16(acc[13], ah, bl[1], bl[3]);
                mma_bf16(acc[12], al, bh[0], bh[2]);
                mma_bf16(acc[13], al, bh[1], bh[3]);
            }
        }
        __syncthreads();
    }

    // epilogue: fp32 partials
    int r0 = pb + wm * 16 + (l >> 2);
    int cb2 = (l & 3) * 2;
    float* Wp = g_Wpart + (size_t)blockIdx.y * HW * NV;
#pragma unroll
    for (int np = 0; np < 7; np++) {
#pragma unroll
        for (int n8 = 0; n8 < 2; n8++) {
            int col = wn * 112 + np * 16 + n8 * 8 + cb2;
            float* a = acc[np * 2 + n8];
            *(float2*)&Wp[(size_t)r0 * NV + col]       = make_float2(a[0], a[1]);
            *(float2*)&Wp[(size_t)(r0 + 8) * NV + col] = make_float2(a[2], a[3]);
        }
    }
}

// ---------------- 7b) reduce W partials ----------------
__global__ void k_Wred() {
    int idx = blockIdx.x * 256 + threadIdx.x;
    if (idx >= HW * NV) return;
    float s = 0.f;
#pragma unroll
    for (int ks = 0; ks < 4; ks++)
        s += g_Wpart[(size_t)ks * HW * NV + idx];
    g_W[idx] = s;
}

// ---------------- 8) combine ----------------
__global__ void k_combine() {
    int idx = blockIdx.x * 256 + threadIdx.x;   // p*64 + c
    if (idx >= HW * CO) return;
    int p = idx >> 6, c = idx & 63;
    float comb = 0.f, msum = 0.f;
#pragma unroll
    for (int k = 0; k < 3; k++) {
        if (g_maskA[k * HW + p]) {
            msum += 1.f;
            float E = g_W[p * NV + 192 + k];
            float denom = E + (4096.0f - g_nbk[k]);
            comb += (g_W[p * NV + k * 64 + c] + g_U0[c] - g_Bk[k * CO + c]) / denom;
        }
    }
    g_aligned[idx] = comb / fmaxf(msum, 1.0f);
}

// ---------------- 9) bilinear upsample 64 -> 256 ----------------
__global__ void k_up(float* __restrict__ out) {
    int idx = blockIdx.x * 256 + threadIdx.x;
    if (idx >= CO * 65536) return;
    int c = idx >> 16, Y = (idx >> 8) & 255, X = idx & 255;
    const float sc = 63.0f / 255.0f;
    float ry = (float)Y * sc, rx = (float)X * sc;
    int y0 = (int)ry, x0 = (int)rx;
    int y1 = min(y0 + 1, 63), x1 = min(x0 + 1, 63);
    float wy = ry - (float)y0, wx = rx - (float)x0;
    const float* A = g_aligned;
    float v00 = A[((y0 << 6) + x0) * CO + c];
    float v01 = A[((y0 << 6) + x1) * CO + c];
    float v10 = A[((y1 << 6) + x0) * CO + c];
    float v11 = A[((y1 << 6) + x1) * CO + c];
    float r0 = v00 * (1.f - wy) + v10 * wy;
    float r1 = v01 * (1.f - wy) + v11 * wy;
    out[idx] = r0 * (1.f - wx) + r1 * wx;
}

// ---------------- launch ----------------
extern "C" void kernel_launch(void* const* d_in, const int* in_sizes, int n_in,
                              void* d_out, int out_size) {
    const float* ufb_in = (const float*)d_in[0];   // (1,64,256,256)
    const float* fa     = (const float*)d_in[1];   // (1,256,64,64)
    const int*   fap    = (const int*)  d_in[2];   // (1,4,256,256)
    const float* fb     = (const float*)d_in[3];   // (1,256,64,64)
    const int*   fbp    = (const int*)  d_in[4];   // (1,4,256,256)
    float* out = (float*)d_out;                    // (1,64,256,256)

    cudaFuncSetAttribute(k_gemm_mma, cudaFuncAttributeMaxDynamicSharedMemorySize, G1_SMEM);
    cudaFuncSetAttribute(k_gemm2,    cudaFuncAttributeMaxDynamicSharedMemorySize, G2_SMEM);

    k_masks<<<16, 256>>>(fap, fbp);
    k_mean<<<512, 256>>>(fa, fb);
    k_norm<<<dim3(16, 2), 256>>>(fa, fb);
    k_gemm_mma<<<dim3(32, 32), 256, G1_SMEM>>>();          // 4th launch -> profiled
    k_ufb<<<(HW * CO) / 256, 256>>>(ufb_in);
    k_ub<<<64, 256>>>();
    k_V<<<(NV * HW) / 256, 256>>>();
    k_gemm2<<<dim3(64, 4), 256, G2_SMEM>>>();
    k_Wred<<<(HW * NV) / 256, 256>>>();
    k_combine<<<(HW * CO) / 256, 256>>>();
    k_up<<<(CO * 65536) / 256, 256>>>(out);
}